// round 14
// baseline (speedup 1.0000x reference)
#include <cuda_runtime.h>
#include <stdint.h>
#include <math.h>

#define NN 50000
#define EE 800000
#define STRIDE 96   // fixed CSR bucket stride; max degree ~45 (Binomial(800k,1/50k))

typedef unsigned long long ull;

// ---------------- scratch (static device globals; no allocs) ----------------
__device__ float  g_z1  [NN * 128];  // conv1 gather table: x@W1a + b1 + pos@Wp1
__device__ float  g_z2  [NN * 128];  // conv2 gather table
__device__ float  g_skip[NN * 128];
__device__ float  g_agg1[NN * 128];
__device__ float  g_agg2[NN * 128];
__device__ float4 g_pos4[NN];
__device__ int    g_deg [NN];
__device__ __align__(16) int g_csr [NN * STRIDE];
__device__ float  g_part[3 * 64 * 256];  // 64-way replicated [inst][rep]{sum[128],sumsq[128]}
__device__ float  g_stat[3 * 256];       // reduced stats

// ---------------- packed fp32x2 helpers (Blackwell FFMA2; bit-exact per lane) ----------------
__device__ __forceinline__ ull pack2(float x) {
    ull r;
    asm("mov.b64 %0, {%1, %1};" : "=l"(r) : "f"(x));
    return r;
}
__device__ __forceinline__ void ffma2(ull& d, ull a, ull b) {
    asm("fma.rn.f32x2 %0, %1, %2, %3;" : "=l"(d) : "l"(a), "l"(b), "l"(d));
}
__device__ __forceinline__ void unpack2(ull v, float& lo, float& hi) {
    asm("mov.b64 {%0, %1}, %2;" : "=f"(lo), "=f"(hi) : "l"(v));
}

// ---------------- init + pack pos ----------------
__global__ void k_init(const float* __restrict__ pos) {
    int i = blockIdx.x * 256 + threadIdx.x;
    if (i < NN) {
        g_deg[i] = 0;
        g_pos4[i] = make_float4(pos[i * 3], pos[i * 3 + 1], pos[i * 3 + 2], 0.0f);
    }
    if (i < 3 * 64 * 256) g_part[i] = 0.0f;
}

// ---------------- one-pass CSR build (fixed-stride buckets) ----------------
__global__ void k_build(const int* __restrict__ ei) {
    int e = blockIdx.x * 256 + threadIdx.x;
    if (e < EE) {
        int s = ei[e];
        int d = ei[EE + e];
        int p = atomicAdd(&g_deg[d], 1);
        g_csr[d * STRIDE + p] = s;
    }
}

// ---------------- reduce 64 replicated partials -> g_stat (two insts per launch) ----------------
__global__ void k_red2(int ia, int ib) {
    int t = threadIdx.x;                 // 512 threads
    int inst = (t < 256) ? ia : ib;
    int c = t & 255;
    if (inst < 0) return;
    const float* p = g_part + inst * 64 * 256 + c;
    float s = 0.0f;
#pragma unroll
    for (int r = 0; r < 64; r++) s += p[r * 256];
    g_stat[inst * 256 + c] = s;
}

// ---------------- GEMM1: z1 = x@W1a + b1 + pos@Wp1 ; skip = x@Wl + bl (+skip stats) ----------------
__global__ __launch_bounds__(256) void k_gemm1(const float* __restrict__ x,
                                               const float* __restrict__ W1,
                                               const float* __restrict__ b1,
                                               const float* __restrict__ Wl,
                                               const float* __restrict__ bl) {
    __shared__ float Xs[64][36];
    __shared__ float Wc[32][256];       // reused as stats scratch after mainloop
    int t  = threadIdx.x;
    int m0 = blockIdx.x * 64;
    int tr = t >> 5;   // 0..7
    int tc = t & 31;   // 0..31
    ull acc2[8][4];
#pragma unroll
    for (int i = 0; i < 8; i++)
#pragma unroll
        for (int j = 0; j < 4; j++) acc2[i][j] = 0ULL;

    for (int kb = 0; kb < 64; kb += 32) {
        {
            int r  = t >> 2;
            int c0 = (t & 3) * 8;
            int row = m0 + r;
            float4 v0 = make_float4(0, 0, 0, 0), v1 = v0;
            if (row < NN) {
                const float4* p = (const float4*)(x + row * 64 + kb + c0);
                v0 = p[0];
                v1 = p[1];
            }
            *(float4*)&Xs[r][c0]     = v0;
            *(float4*)&Xs[r][c0 + 4] = v1;
        }
        {
            int k   = t >> 3;
            int c0w = (t & 7) * 32;
#pragma unroll
            for (int j = 0; j < 32; j += 4) {
                int c = c0w + j;
                float4 w;
                if (c < 128) w = *(const float4*)(W1 + (kb + k) * 128 + c);
                else         w = *(const float4*)(Wl + (kb + k) * 128 + (c - 128));
                *(float4*)&Wc[k][c] = w;
            }
        }
        __syncthreads();
#pragma unroll
        for (int k2 = 0; k2 < 32; k2++) {
            const ull* bp = (const ull*)&Wc[k2][tc * 8];
            ull b0 = bp[0], b1v = bp[1], b2v = bp[2], b3 = bp[3];
#pragma unroll
            for (int i = 0; i < 8; i++) {
                ull a2 = pack2(Xs[tr * 8 + i][k2]);
                ffma2(acc2[i][0], a2, b0);
                ffma2(acc2[i][1], a2, b1v);
                ffma2(acc2[i][2], a2, b2v);
                ffma2(acc2[i][3], a2, b3);
            }
        }
        __syncthreads();   // also guards Wc reuse below
    }

    // unpack accumulators
    float acc[8][8];
#pragma unroll
    for (int i = 0; i < 8; i++)
#pragma unroll
        for (int j = 0; j < 4; j++)
            unpack2(acc2[i][j], acc[i][2 * j], acc[i][2 * j + 1]);

    float* shs = (float*)Wc;           // [8][128]
    float* shq = shs + 1024;           // [8][128]
    int c0 = tc * 8;
    float bias[8];
#pragma unroll
    for (int j = 0; j < 8; j++) {
        int c = c0 + j;
        bias[j] = (c < 128) ? b1[c] : bl[c - 128];
    }
    if (c0 < 128) {
        // z1 columns: fold in pos@Wp1 (Wp1 = rows 64..66 of W1)
        const float* Wp = W1 + 64 * 128;
        float4 wx0 = *(const float4*)(Wp + c0);
        float4 wx1 = *(const float4*)(Wp + c0 + 4);
        float4 wy0 = *(const float4*)(Wp + 128 + c0);
        float4 wy1 = *(const float4*)(Wp + 128 + c0 + 4);
        float4 wz0 = *(const float4*)(Wp + 256 + c0);
        float4 wz1 = *(const float4*)(Wp + 256 + c0 + 4);
#pragma unroll
        for (int i = 0; i < 8; i++) {
            int row = m0 + tr * 8 + i;
            if (row >= NN) continue;
            float4 p = g_pos4[row];
            float4 o0, o1;
            o0.x = acc[i][0] + bias[0] + p.x * wx0.x + p.y * wy0.x + p.z * wz0.x;
            o0.y = acc[i][1] + bias[1] + p.x * wx0.y + p.y * wy0.y + p.z * wz0.y;
            o0.z = acc[i][2] + bias[2] + p.x * wx0.z + p.y * wy0.z + p.z * wz0.z;
            o0.w = acc[i][3] + bias[3] + p.x * wx0.w + p.y * wy0.w + p.z * wz0.w;
            o1.x = acc[i][4] + bias[4] + p.x * wx1.x + p.y * wy1.x + p.z * wz1.x;
            o1.y = acc[i][5] + bias[5] + p.x * wx1.y + p.y * wy1.y + p.z * wz1.y;
            o1.z = acc[i][6] + bias[6] + p.x * wx1.z + p.y * wy1.z + p.z * wz1.z;
            o1.w = acc[i][7] + bias[7] + p.x * wx1.w + p.y * wy1.w + p.z * wz1.w;
            *(float4*)(g_z1 + row * 128 + c0)     = o0;
            *(float4*)(g_z1 + row * 128 + c0 + 4) = o1;
        }
    } else {
        // skip columns + per-column stats partials
        float sj[8], qj[8];
#pragma unroll
        for (int j = 0; j < 8; j++) { sj[j] = 0.0f; qj[j] = 0.0f; }
#pragma unroll
        for (int i = 0; i < 8; i++) {
            int row = m0 + tr * 8 + i;
            if (row >= NN) continue;
            float4 o0, o1;
            o0.x = acc[i][0] + bias[0]; o0.y = acc[i][1] + bias[1];
            o0.z = acc[i][2] + bias[2]; o0.w = acc[i][3] + bias[3];
            o1.x = acc[i][4] + bias[4]; o1.y = acc[i][5] + bias[5];
            o1.z = acc[i][6] + bias[6]; o1.w = acc[i][7] + bias[7];
            *(float4*)(g_skip + row * 128 + (c0 - 128))     = o0;
            *(float4*)(g_skip + row * 128 + (c0 - 128) + 4) = o1;
            sj[0] += o0.x; qj[0] += o0.x * o0.x;
            sj[1] += o0.y; qj[1] += o0.y * o0.y;
            sj[2] += o0.z; qj[2] += o0.z * o0.z;
            sj[3] += o0.w; qj[3] += o0.w * o0.w;
            sj[4] += o1.x; qj[4] += o1.x * o1.x;
            sj[5] += o1.y; qj[5] += o1.y * o1.y;
            sj[6] += o1.z; qj[6] += o1.z * o1.z;
            sj[7] += o1.w; qj[7] += o1.w * o1.w;
        }
        int csk = c0 - 128;
#pragma unroll
        for (int j = 0; j < 8; j++) {
            shs[tr * 128 + csk + j] = sj[j];
            shq[tr * 128 + csk + j] = qj[j];
        }
    }
    __syncthreads();
    if (t < 128) {
        float a = 0.0f, b = 0.0f;
#pragma unroll
        for (int w2 = 0; w2 < 8; w2++) {
            a += shs[w2 * 128 + t];
            b += shq[w2 * 128 + t];
        }
        float* st = g_part + (blockIdx.x & 63) * 256;   // inst 0
        atomicAdd(&st[t], a);
        atomicAdd(&st[128 + t], b);
    }
}

// ---------------- GEMM2: z2 = relu(BN1(agg1))@W2a + b2 + pos@Wp2 (BN1 inlined) ----------------
__global__ __launch_bounds__(256) void k_gemm2(const float* __restrict__ W2,
                                               const float* __restrict__ b2,
                                               const float* __restrict__ g1,
                                               const float* __restrict__ be1) {
    __shared__ float Xs[128][36];
    __shared__ float Ws[32][128];
    __shared__ float sc[128], sf[128];
    int t = threadIdx.x;
    if (t < 128) {
        float mu  = g_stat[256 + t] * (1.0f / NN);
        float var = g_stat[256 + 128 + t] * (1.0f / NN) - mu * mu;
        float rs  = rsqrtf(var + 1e-5f);
        float scale = g1[t] * rs;
        sc[t] = scale;
        sf[t] = be1[t] - mu * scale;
    }
    int m0 = blockIdx.x * 128;
    int tr = t >> 4;
    int tc = t & 15;
    ull acc2[8][4];
#pragma unroll
    for (int i = 0; i < 8; i++)
#pragma unroll
        for (int j = 0; j < 4; j++) acc2[i][j] = 0ULL;
    __syncthreads();

    for (int kb = 0; kb < 128; kb += 32) {
        {
            int r  = t >> 1;
            int c0 = (t & 1) * 16;
            int row = m0 + r;
#pragma unroll
            for (int j = 0; j < 16; j += 4) {
                int kk = c0 + j;
                int kg = kb + kk;
                float4 v = make_float4(0, 0, 0, 0);
                if (row < NN) v = *(const float4*)(g_agg1 + row * 128 + kg);
                v.x = fmaxf(fmaf(v.x, sc[kg],     sf[kg]),     0.0f);
                v.y = fmaxf(fmaf(v.y, sc[kg + 1], sf[kg + 1]), 0.0f);
                v.z = fmaxf(fmaf(v.z, sc[kg + 2], sf[kg + 2]), 0.0f);
                v.w = fmaxf(fmaf(v.w, sc[kg + 3], sf[kg + 3]), 0.0f);
                *(float4*)&Xs[r][kk] = v;
            }
        }
        {
            int kw = t >> 3;
            int cw = (t & 7) * 16;
#pragma unroll
            for (int j = 0; j < 16; j += 4)
                *(float4*)&Ws[kw][cw + j] = *(const float4*)(W2 + (kb + kw) * 128 + cw + j);
        }
        __syncthreads();
#pragma unroll
        for (int k2 = 0; k2 < 32; k2++) {
            const ull* bp = (const ull*)&Ws[k2][tc * 8];
            ull b0 = bp[0], b1v = bp[1], b2v = bp[2], b3 = bp[3];
#pragma unroll
            for (int i = 0; i < 8; i++) {
                ull a2 = pack2(Xs[tr * 8 + i][k2]);
                ffma2(acc2[i][0], a2, b0);
                ffma2(acc2[i][1], a2, b1v);
                ffma2(acc2[i][2], a2, b2v);
                ffma2(acc2[i][3], a2, b3);
            }
        }
        __syncthreads();
    }

    float acc[8][8];
#pragma unroll
    for (int i = 0; i < 8; i++)
#pragma unroll
        for (int j = 0; j < 4; j++)
            unpack2(acc2[i][j], acc[i][2 * j], acc[i][2 * j + 1]);

    int c0 = tc * 8;
    float4 bb0 = *(const float4*)(b2 + c0);
    float4 bb1 = *(const float4*)(b2 + c0 + 4);
    const float* Wp = W2 + 128 * 128;
    float4 wx0 = *(const float4*)(Wp + c0);
    float4 wx1 = *(const float4*)(Wp + c0 + 4);
    float4 wy0 = *(const float4*)(Wp + 128 + c0);
    float4 wy1 = *(const float4*)(Wp + 128 + c0 + 4);
    float4 wz0 = *(const float4*)(Wp + 256 + c0);
    float4 wz1 = *(const float4*)(Wp + 256 + c0 + 4);
#pragma unroll
    for (int i = 0; i < 8; i++) {
        int row = m0 + tr * 8 + i;
        if (row >= NN) continue;
        float4 p = g_pos4[row];
        float4 o0, o1;
        o0.x = acc[i][0] + bb0.x + p.x * wx0.x + p.y * wy0.x + p.z * wz0.x;
        o0.y = acc[i][1] + bb0.y + p.x * wx0.y + p.y * wy0.y + p.z * wz0.y;
        o0.z = acc[i][2] + bb0.z + p.x * wx0.z + p.y * wy0.z + p.z * wz0.z;
        o0.w = acc[i][3] + bb0.w + p.x * wx0.w + p.y * wy0.w + p.z * wz0.w;
        o1.x = acc[i][4] + bb1.x + p.x * wx1.x + p.y * wy1.x + p.z * wz1.x;
        o1.y = acc[i][5] + bb1.y + p.x * wx1.y + p.y * wy1.y + p.z * wz1.y;
        o1.z = acc[i][6] + bb1.z + p.x * wx1.z + p.y * wy1.z + p.z * wz1.z;
        o1.w = acc[i][7] + bb1.w + p.x * wx1.w + p.y * wy1.w + p.z * wz1.w;
        *(float4*)(g_z2 + row * 128 + c0)     = o0;
        *(float4*)(g_z2 + row * 128 + c0 + 4) = o1;
    }
}

// ---------------- aggregation: one warp per dst, gather+max, diluted stats ----------------
__global__ __launch_bounds__(256) void k_agg(const float* __restrict__ Wp, int phase, int inst) {
    __shared__ float shs[8][128];
    __shared__ float shq[8][128];
    int w    = threadIdx.x >> 5;
    int gw   = blockIdx.x * 8 + w;              // grid exact: gw < NN
    int lane = threadIdx.x & 31;
    int f = lane * 4;
    const float* __restrict__ z = phase ? g_z2 : g_z1;
    int cnt = g_deg[gw];
    const int* __restrict__ bucket = g_csr + gw * STRIDE;
    float ninf = __int_as_float(0xff800000);
    float4 acc = make_float4(ninf, ninf, ninf, ninf);
#pragma unroll 8
    for (int e = 0; e < cnt; e++) {
        int s = __ldg(&bucket[e]);
        float4 v = *(const float4*)(z + s * 128 + f);
        acc.x = fmaxf(acc.x, v.x);
        acc.y = fmaxf(acc.y, v.y);
        acc.z = fmaxf(acc.z, v.z);
        acc.w = fmaxf(acc.w, v.w);
    }
    float4 o;
    if (cnt == 0) {
        o = make_float4(0, 0, 0, 0);
    } else {
        float4 dp = g_pos4[gw];
        float4 wx = *(const float4*)(Wp + f);
        float4 wy = *(const float4*)(Wp + 128 + f);
        float4 wz = *(const float4*)(Wp + 256 + f);
        o.x = acc.x - (dp.x * wx.x + dp.y * wy.x + dp.z * wz.x);
        o.y = acc.y - (dp.x * wx.y + dp.y * wy.y + dp.z * wz.y);
        o.z = acc.z - (dp.x * wx.z + dp.y * wy.z + dp.z * wz.z);
        o.w = acc.w - (dp.x * wx.w + dp.y * wy.w + dp.z * wz.w);
    }
    float* oo = phase ? g_agg2 : g_agg1;
    *(float4*)(oo + gw * 128 + f) = o;

    // fused column stats -> 64-way replicated partials
    *(float4*)&shs[w][f] = o;
    float4 q = make_float4(o.x * o.x, o.y * o.y, o.z * o.z, o.w * o.w);
    *(float4*)&shq[w][f] = q;
    __syncthreads();
    int t = threadIdx.x;
    if (t < 128) {
        float a = 0.0f, b = 0.0f;
#pragma unroll
        for (int w2 = 0; w2 < 8; w2++) {
            a += shs[w2][t];
            b += shq[w2][t];
        }
        float* st = g_part + (inst * 64 + (blockIdx.x & 63)) * 256;
        atomicAdd(&st[t], a);
        atomicAdd(&st[128 + t], b);
    }
}

// ---------------- output: relu(BN2(agg2) + BNl(skip)), BN inlined ----------------
__global__ __launch_bounds__(256) void k_out(float* __restrict__ out,
                                             const float* __restrict__ gl,
                                             const float* __restrict__ bel,
                                             const float* __restrict__ g2,
                                             const float* __restrict__ be2) {
    __shared__ float cl[128], hl[128], c2[128], h2[128];
    int t = threadIdx.x;
    if (t < 128) {
        float mu  = g_stat[t] * (1.0f / NN);
        float var = g_stat[128 + t] * (1.0f / NN) - mu * mu;
        float rs  = rsqrtf(var + 1e-5f);
        float s0  = gl[t] * rs;
        cl[t] = s0;
        hl[t] = bel[t] - mu * s0;
    } else {
        int f = t - 128;
        float mu  = g_stat[512 + f] * (1.0f / NN);
        float var = g_stat[512 + 128 + f] * (1.0f / NN) - mu * mu;
        float rs  = rsqrtf(var + 1e-5f);
        float s2  = g2[f] * rs;
        c2[f] = s2;
        h2[f] = be2[f] - mu * s2;
    }
    __syncthreads();
    int i = blockIdx.x * 8 + (t >> 5);
    int f = (t & 31) * 4;
    float4 a  = *(const float4*)(g_agg2 + i * 128 + f);
    float4 s  = *(const float4*)(g_skip + i * 128 + f);
    float4 o;
    o.x = fmaxf(fmaf(a.x, c2[f],     h2[f])     + fmaf(s.x, cl[f],     hl[f]),     0.0f);
    o.y = fmaxf(fmaf(a.y, c2[f + 1], h2[f + 1]) + fmaf(s.y, cl[f + 1], hl[f + 1]), 0.0f);
    o.z = fmaxf(fmaf(a.z, c2[f + 2], h2[f + 2]) + fmaf(s.z, cl[f + 2], hl[f + 2]), 0.0f);
    o.w = fmaxf(fmaf(a.w, c2[f + 3], h2[f + 3]) + fmaf(s.w, cl[f + 3], hl[f + 3]), 0.0f);
    *(float4*)(out + i * 128 + f) = o;
}

// ---------------- launcher ----------------
extern "C" void kernel_launch(void* const* d_in, const int* in_sizes, int n_in,
                              void* d_out, int out_size) {
    const float* x   = (const float*)d_in[0];
    const float* pos = (const float*)d_in[1];
    const int*   ei  = (const int*)  d_in[2];
    const float* W1  = (const float*)d_in[3];
    const float* b1  = (const float*)d_in[4];
    const float* g1  = (const float*)d_in[5];
    const float* be1 = (const float*)d_in[6];
    const float* W2  = (const float*)d_in[7];
    const float* b2  = (const float*)d_in[8];
    const float* g2  = (const float*)d_in[9];
    const float* be2 = (const float*)d_in[10];
    const float* Wl  = (const float*)d_in[11];
    const float* bl  = (const float*)d_in[12];
    const float* gl  = (const float*)d_in[13];
    const float* bel = (const float*)d_in[14];
    float* out = (float*)d_out;

    int gridE = (EE + 255) / 256;
    int gridN = (NN + 255) / 256;
    int gridA = NN / 8;                 // 6250 (8 warps/block, 1 node/warp)

    k_init<<<gridN, 256>>>(pos);
    k_build<<<gridE, 256>>>(ei);

    k_gemm1<<<(NN + 63) / 64, 256>>>(x, W1, b1, Wl, bl);      // + skip stats (inst 0, replicated)

    k_agg<<<gridA, 256>>>(W1 + 64 * 128, 0, 1);               // + agg1 stats (inst 1, replicated)
    k_red2<<<1, 512>>>(0, 1);                                 // fold partials for inst 0 & 1

    k_gemm2<<<(NN + 127) / 128, 256>>>(W2, b2, g1, be1);      // BN1 inlined

    k_agg<<<gridA, 256>>>(W2 + 128 * 128, 1, 2);              // + agg2 stats (inst 2, replicated)
    k_red2<<<1, 512>>>(2, -1);                                // fold partials for inst 2

    k_out<<<gridA, 256>>>(out, gl, bel, g2, be2);             // BN0 + BN2 inlined
}

// round 15
// speedup vs baseline: 1.1089x; 1.1089x over previous
#include <cuda_runtime.h>
#include <cuda_bf16.h>
#include <stdint.h>
#include <math.h>

#define NN 50000
#define EE 800000
#define STRIDE 96   // fixed CSR bucket stride; max degree ~45 (Binomial(800k,1/50k))

// padded row stride (in 32-bit words) for bf16-pair tiles: 64 data + 4 pad -> bank map 4g+c, conflict-free
#define PSTR 68

// ---------------- scratch (static device globals; no allocs) ----------------
__device__ float    g_z1  [NN * 128];  // conv1 gather table: x@W1a + b1 + pos@Wp1
__device__ float    g_z2  [NN * 128];  // conv2 gather table
__device__ float    g_skip[NN * 128];
__device__ float    g_agg1[NN * 128];
__device__ float    g_agg2[NN * 128];
__device__ float4   g_pos4[NN];
__device__ int      g_deg [NN];
__device__ __align__(16) int g_csr [NN * STRIDE];
__device__ float    g_part[3 * 64 * 256];  // 64-way replicated [inst][rep]{sum[128],sumsq[128]}
__device__ float    g_stat[3 * 256];       // reduced stats
__device__ __align__(16) uint32_t g_bh[128 * PSTR];  // W2^T bf16 hi, [n][k-pair], padded
__device__ __align__(16) uint32_t g_bl[128 * PSTR];  // W2^T bf16 lo

// ---------------- bf16 mma.sync m16n8k16 (sm_80+ legal on plain sm_100) ----------------
__device__ __forceinline__ void mma_bf16(float& c0, float& c1, float& c2, float& c3,
                                         uint32_t a0, uint32_t a1, uint32_t a2, uint32_t a3,
                                         uint32_t b0, uint32_t b1) {
    asm volatile(
        "mma.sync.aligned.m16n8k16.row.col.f32.bf16.bf16.f32 "
        "{%0,%1,%2,%3}, {%4,%5,%6,%7}, {%8,%9}, {%0,%1,%2,%3};"
        : "+f"(c0), "+f"(c1), "+f"(c2), "+f"(c3)
        : "r"(a0), "r"(a1), "r"(a2), "r"(a3), "r"(b0), "r"(b1));
}
__device__ __forceinline__ uint32_t pack_bf16x2(float lo, float hi) {
    __nv_bfloat162 h;
    h.x = __float2bfloat16(lo);
    h.y = __float2bfloat16(hi);
    return *(uint32_t*)&h;
}

// ---------------- init + pack pos ----------------
__global__ void k_init(const float* __restrict__ pos) {
    int i = blockIdx.x * 256 + threadIdx.x;
    if (i < NN) {
        g_deg[i] = 0;
        g_pos4[i] = make_float4(pos[i * 3], pos[i * 3 + 1], pos[i * 3 + 2], 0.0f);
    }
    if (i < 3 * 64 * 256) g_part[i] = 0.0f;
}

// ---------------- one-pass CSR build (fixed-stride buckets) ----------------
__global__ void k_build(const int* __restrict__ ei) {
    int e = blockIdx.x * 256 + threadIdx.x;
    if (e < EE) {
        int s = ei[e];
        int d = ei[EE + e];
        int p = atomicAdd(&g_deg[d], 1);
        g_csr[d * STRIDE + p] = s;
    }
}

// ---------------- W2 -> transposed bf16 hi/lo padded image ----------------
__global__ void k_prepW(const float* __restrict__ W2) {
    int idx = blockIdx.x * 256 + threadIdx.x;   // (n, kpair): 128 * 64
    if (idx >= 128 * 64) return;
    int n = idx >> 6, kp = idx & 63, k = kp * 2;
    float v0 = W2[k * 128 + n];
    float v1 = W2[(k + 1) * 128 + n];
    __nv_bfloat16 h0 = __float2bfloat16(v0);
    __nv_bfloat16 h1 = __float2bfloat16(v1);
    float l0f = v0 - __bfloat162float(h0);
    float l1f = v1 - __bfloat162float(h1);
    __nv_bfloat162 hh; hh.x = h0; hh.y = h1;
    g_bh[n * PSTR + kp] = *(uint32_t*)&hh;
    g_bl[n * PSTR + kp] = pack_bf16x2(l0f, l1f);
}

// ---------------- reduce 64 replicated partials -> g_stat (two insts per launch) ----------------
__global__ void k_red2(int ia, int ib) {
    int t = threadIdx.x;                 // 512 threads
    int inst = (t < 256) ? ia : ib;
    int c = t & 255;
    if (inst < 0) return;
    const float* p = g_part + inst * 64 * 256 + c;
    float s = 0.0f;
#pragma unroll
    for (int r = 0; r < 64; r++) s += p[r * 256];
    g_stat[inst * 256 + c] = s;
}

// ---------------- GEMM1 (scalar, R10): z1 = x@W1a + b1 + pos@Wp1 ; skip = x@Wl + bl ----------------
__global__ __launch_bounds__(256) void k_gemm1(const float* __restrict__ x,
                                               const float* __restrict__ W1,
                                               const float* __restrict__ b1,
                                               const float* __restrict__ Wl,
                                               const float* __restrict__ bl) {
    __shared__ float Xs[64][36];
    __shared__ float Wc[32][256];       // reused as stats scratch after mainloop
    int t  = threadIdx.x;
    int m0 = blockIdx.x * 64;
    int tr = t >> 5;
    int tc = t & 31;
    float acc[8][8];
#pragma unroll
    for (int i = 0; i < 8; i++)
#pragma unroll
        for (int j = 0; j < 8; j++) acc[i][j] = 0.0f;

    for (int kb = 0; kb < 64; kb += 32) {
        {
            int r  = t >> 2;
            int c0 = (t & 3) * 8;
            int row = m0 + r;
            float4 v0 = make_float4(0, 0, 0, 0), v1 = v0;
            if (row < NN) {
                const float4* p = (const float4*)(x + row * 64 + kb + c0);
                v0 = p[0];
                v1 = p[1];
            }
            *(float4*)&Xs[r][c0]     = v0;
            *(float4*)&Xs[r][c0 + 4] = v1;
        }
        {
            int k   = t >> 3;
            int c0w = (t & 7) * 32;
#pragma unroll
            for (int j = 0; j < 32; j += 4) {
                int c = c0w + j;
                float4 w;
                if (c < 128) w = *(const float4*)(W1 + (kb + k) * 128 + c);
                else         w = *(const float4*)(Wl + (kb + k) * 128 + (c - 128));
                *(float4*)&Wc[k][c] = w;
            }
        }
        __syncthreads();
#pragma unroll
        for (int k2 = 0; k2 < 32; k2++) {
            float a[8];
#pragma unroll
            for (int i = 0; i < 8; i++) a[i] = Xs[tr * 8 + i][k2];
            float4 bv0 = *(float4*)&Wc[k2][tc * 8];
            float4 bv1 = *(float4*)&Wc[k2][tc * 8 + 4];
            float b[8] = {bv0.x, bv0.y, bv0.z, bv0.w, bv1.x, bv1.y, bv1.z, bv1.w};
#pragma unroll
            for (int i = 0; i < 8; i++)
#pragma unroll
                for (int j = 0; j < 8; j++) acc[i][j] = fmaf(a[i], b[j], acc[i][j]);
        }
        __syncthreads();
    }

    float* shs = (float*)Wc;
    float* shq = shs + 1024;
    int c0 = tc * 8;
    float bias[8];
#pragma unroll
    for (int j = 0; j < 8; j++) {
        int c = c0 + j;
        bias[j] = (c < 128) ? b1[c] : bl[c - 128];
    }
    if (c0 < 128) {
        const float* Wp = W1 + 64 * 128;
        float4 wx0 = *(const float4*)(Wp + c0);
        float4 wx1 = *(const float4*)(Wp + c0 + 4);
        float4 wy0 = *(const float4*)(Wp + 128 + c0);
        float4 wy1 = *(const float4*)(Wp + 128 + c0 + 4);
        float4 wz0 = *(const float4*)(Wp + 256 + c0);
        float4 wz1 = *(const float4*)(Wp + 256 + c0 + 4);
#pragma unroll
        for (int i = 0; i < 8; i++) {
            int row = m0 + tr * 8 + i;
            if (row >= NN) continue;
            float4 p = g_pos4[row];
            float4 o0, o1;
            o0.x = acc[i][0] + bias[0] + p.x * wx0.x + p.y * wy0.x + p.z * wz0.x;
            o0.y = acc[i][1] + bias[1] + p.x * wx0.y + p.y * wy0.y + p.z * wz0.y;
            o0.z = acc[i][2] + bias[2] + p.x * wx0.z + p.y * wy0.z + p.z * wz0.z;
            o0.w = acc[i][3] + bias[3] + p.x * wx0.w + p.y * wy0.w + p.z * wz0.w;
            o1.x = acc[i][4] + bias[4] + p.x * wx1.x + p.y * wy1.x + p.z * wz1.x;
            o1.y = acc[i][5] + bias[5] + p.x * wx1.y + p.y * wy1.y + p.z * wz1.y;
            o1.z = acc[i][6] + bias[6] + p.x * wx1.z + p.y * wy1.z + p.z * wz1.z;
            o1.w = acc[i][7] + bias[7] + p.x * wx1.w + p.y * wy1.w + p.z * wz1.w;
            *(float4*)(g_z1 + row * 128 + c0)     = o0;
            *(float4*)(g_z1 + row * 128 + c0 + 4) = o1;
        }
    } else {
        float sj[8], qj[8];
#pragma unroll
        for (int j = 0; j < 8; j++) { sj[j] = 0.0f; qj[j] = 0.0f; }
#pragma unroll
        for (int i = 0; i < 8; i++) {
            int row = m0 + tr * 8 + i;
            if (row >= NN) continue;
            float4 o0, o1;
            o0.x = acc[i][0] + bias[0]; o0.y = acc[i][1] + bias[1];
            o0.z = acc[i][2] + bias[2]; o0.w = acc[i][3] + bias[3];
            o1.x = acc[i][4] + bias[4]; o1.y = acc[i][5] + bias[5];
            o1.z = acc[i][6] + bias[6]; o1.w = acc[i][7] + bias[7];
            *(float4*)(g_skip + row * 128 + (c0 - 128))     = o0;
            *(float4*)(g_skip + row * 128 + (c0 - 128) + 4) = o1;
            sj[0] += o0.x; qj[0] += o0.x * o0.x;
            sj[1] += o0.y; qj[1] += o0.y * o0.y;
            sj[2] += o0.z; qj[2] += o0.z * o0.z;
            sj[3] += o0.w; qj[3] += o0.w * o0.w;
            sj[4] += o1.x; qj[4] += o1.x * o1.x;
            sj[5] += o1.y; qj[5] += o1.y * o1.y;
            sj[6] += o1.z; qj[6] += o1.z * o1.z;
            sj[7] += o1.w; qj[7] += o1.w * o1.w;
        }
        int csk = c0 - 128;
#pragma unroll
        for (int j = 0; j < 8; j++) {
            shs[tr * 128 + csk + j] = sj[j];
            shq[tr * 128 + csk + j] = qj[j];
        }
    }
    __syncthreads();
    if (t < 128) {
        float a = 0.0f, b = 0.0f;
#pragma unroll
        for (int w2 = 0; w2 < 8; w2++) {
            a += shs[w2 * 128 + t];
            b += shq[w2 * 128 + t];
        }
        float* st = g_part + (blockIdx.x & 63) * 256;   // inst 0
        atomicAdd(&st[t], a);
        atomicAdd(&st[128 + t], b);
    }
}

// ---------------- GEMM2 (mma.sync bf16 3-term split): z2 = relu(BN1(agg1))@W2a + b2 + pos@Wp2 ----------------
// Block: 128 rows x 128 cols, K=128. 8 warps: warpM = wid&3 (32-row tile), warpN = wid>>2 (64-col tile).
__global__ __launch_bounds__(256, 1) void k_gemm2_mma(const float* __restrict__ W2,
                                                      const float* __restrict__ b2,
                                                      const float* __restrict__ g1,
                                                      const float* __restrict__ be1) {
    extern __shared__ uint32_t sm[];
    uint32_t* Ah = sm;                   // [128][PSTR] bf16 pairs
    uint32_t* Al = Ah + 128 * PSTR;
    uint32_t* Bh = Al + 128 * PSTR;      // [128 n][PSTR]
    uint32_t* Bl = Bh + 128 * PSTR;
    __shared__ float sc[128], sf[128];                 // BN1 scale/shift
    __shared__ float s_bias[128], s_wx[128], s_wy[128], s_wz[128];

    int t = threadIdx.x;
    int m0 = blockIdx.x * 128;
    int lane = t & 31, wid = t >> 5;
    int g = lane >> 2, qc = lane & 3;

    if (t < 128) {
        float mu  = g_stat[256 + t] * (1.0f / NN);
        float var = g_stat[256 + 128 + t] * (1.0f / NN) - mu * mu;
        float rs  = rsqrtf(var + 1e-5f);
        float scale = g1[t] * rs;
        sc[t] = scale;
        sf[t] = be1[t] - mu * scale;
        const float* Wp = W2 + 128 * 128;
        s_bias[t] = b2[t];
        s_wx[t] = Wp[t];
        s_wy[t] = Wp[128 + t];
        s_wz[t] = Wp[256 + t];
    }
    // copy W2 split image into SMEM (zero-init pad words included; deterministic)
    {
        const uint4* srcH = (const uint4*)g_bh;
        const uint4* srcL = (const uint4*)g_bl;
        uint4* dstH = (uint4*)Bh;
        uint4* dstL = (uint4*)Bl;
        for (int i = t; i < 128 * PSTR / 4; i += 256) {
            dstH[i] = srcH[i];
            dstL[i] = srcL[i];
        }
    }
    __syncthreads();

    // convert A tile: BN1+relu, split to bf16 hi/lo
    for (int idx = t; idx < 128 * 64; idx += 256) {
        int row = idx >> 6, kp = idx & 63, k = kp * 2;
        int grow = m0 + row;
        float2 v = make_float2(0.0f, 0.0f);
        if (grow < NN) v = *(const float2*)(g_agg1 + grow * 128 + k);
        float a0 = fmaxf(fmaf(v.x, sc[k],     sf[k]),     0.0f);
        float a1 = fmaxf(fmaf(v.y, sc[k + 1], sf[k + 1]), 0.0f);
        __nv_bfloat16 h0 = __float2bfloat16(a0);
        __nv_bfloat16 h1 = __float2bfloat16(a1);
        __nv_bfloat162 hh; hh.x = h0; hh.y = h1;
        Ah[row * PSTR + kp] = *(uint32_t*)&hh;
        Al[row * PSTR + kp] = pack_bf16x2(a0 - __bfloat162float(h0), a1 - __bfloat162float(h1));
    }
    __syncthreads();

    int warpM = wid & 3, warpN = wid >> 2;
    int rbase = warpM * 32;
    int nbase = warpN * 64;

    float acc[2][8][4];
#pragma unroll
    for (int mi = 0; mi < 2; mi++)
#pragma unroll
        for (int ni = 0; ni < 8; ni++)
#pragma unroll
            for (int j = 0; j < 4; j++) acc[mi][ni][j] = 0.0f;

#pragma unroll
    for (int k0 = 0; k0 < 8; k0++) {
        int kw = k0 * 8 + qc;           // b32 word index within row
        // Ah fragments
        uint32_t ah[2][4];
#pragma unroll
        for (int mi = 0; mi < 2; mi++) {
            int r = rbase + mi * 16 + g;
            ah[mi][0] = Ah[r * PSTR + kw];
            ah[mi][1] = Ah[(r + 8) * PSTR + kw];
            ah[mi][2] = Ah[r * PSTR + kw + 4];
            ah[mi][3] = Ah[(r + 8) * PSTR + kw + 4];
        }
        // Bh fragments
        uint32_t bh[8][2];
#pragma unroll
        for (int ni = 0; ni < 8; ni++) {
            int n = nbase + ni * 8 + g;
            bh[ni][0] = Bh[n * PSTR + kw];
            bh[ni][1] = Bh[n * PSTR + kw + 4];
        }
        // term 1: Ah x Bh
#pragma unroll
        for (int mi = 0; mi < 2; mi++)
#pragma unroll
            for (int ni = 0; ni < 8; ni++)
                mma_bf16(acc[mi][ni][0], acc[mi][ni][1], acc[mi][ni][2], acc[mi][ni][3],
                         ah[mi][0], ah[mi][1], ah[mi][2], ah[mi][3], bh[ni][0], bh[ni][1]);
        // term 2: Al x Bh
#pragma unroll
        for (int mi = 0; mi < 2; mi++) {
            int r = rbase + mi * 16 + g;
            uint32_t al0 = Al[r * PSTR + kw];
            uint32_t al1 = Al[(r + 8) * PSTR + kw];
            uint32_t al2 = Al[r * PSTR + kw + 4];
            uint32_t al3 = Al[(r + 8) * PSTR + kw + 4];
#pragma unroll
            for (int ni = 0; ni < 8; ni++)
                mma_bf16(acc[mi][ni][0], acc[mi][ni][1], acc[mi][ni][2], acc[mi][ni][3],
                         al0, al1, al2, al3, bh[ni][0], bh[ni][1]);
        }
        // term 3: Ah x Bl
#pragma unroll
        for (int ni = 0; ni < 8; ni++) {
            int n = nbase + ni * 8 + g;
            uint32_t bl0 = Bl[n * PSTR + kw];
            uint32_t bl1 = Bl[n * PSTR + kw + 4];
#pragma unroll
            for (int mi = 0; mi < 2; mi++)
                mma_bf16(acc[mi][ni][0], acc[mi][ni][1], acc[mi][ni][2], acc[mi][ni][3],
                         ah[mi][0], ah[mi][1], ah[mi][2], ah[mi][3], bl0, bl1);
        }
    }

    // epilogue: + bias + pos@Wp2, store to g_z2
#pragma unroll
    for (int mi = 0; mi < 2; mi++) {
        int r0 = m0 + rbase + mi * 16 + g;
        int r1 = r0 + 8;
        bool v0 = r0 < NN, v1 = r1 < NN;
        float4 p0 = g_pos4[v0 ? r0 : 0];
        float4 p1 = g_pos4[v1 ? r1 : 0];
#pragma unroll
        for (int ni = 0; ni < 8; ni++) {
            int c = nbase + ni * 8 + qc * 2;
            float bx0 = s_bias[c]     + p0.x * s_wx[c]     + p0.y * s_wy[c]     + p0.z * s_wz[c];
            float bx1 = s_bias[c + 1] + p0.x * s_wx[c + 1] + p0.y * s_wy[c + 1] + p0.z * s_wz[c + 1];
            float by0 = s_bias[c]     + p1.x * s_wx[c]     + p1.y * s_wy[c]     + p1.z * s_wz[c];
            float by1 = s_bias[c + 1] + p1.x * s_wx[c + 1] + p1.y * s_wy[c + 1] + p1.z * s_wz[c + 1];
            if (v0) *(float2*)(g_z2 + r0 * 128 + c) = make_float2(acc[mi][ni][0] + bx0, acc[mi][ni][1] + bx1);
            if (v1) *(float2*)(g_z2 + r1 * 128 + c) = make_float2(acc[mi][ni][2] + by0, acc[mi][ni][3] + by1);
        }
    }
}

// ---------------- aggregation: one warp per dst, gather+max, diluted stats ----------------
__global__ __launch_bounds__(256) void k_agg(const float* __restrict__ Wp, int phase, int inst) {
    __shared__ float shs[8][128];
    __shared__ float shq[8][128];
    int w    = threadIdx.x >> 5;
    int gw   = blockIdx.x * 8 + w;              // grid exact: gw < NN
    int lane = threadIdx.x & 31;
    int f = lane * 4;
    const float* __restrict__ z = phase ? g_z2 : g_z1;
    int cnt = g_deg[gw];
    const int* __restrict__ bucket = g_csr + gw * STRIDE;
    float ninf = __int_as_float(0xff800000);
    float4 acc = make_float4(ninf, ninf, ninf, ninf);
#pragma unroll 8
    for (int e = 0; e < cnt; e++) {
        int s = __ldg(&bucket[e]);
        float4 v = *(const float4*)(z + s * 128 + f);
        acc.x = fmaxf(acc.x, v.x);
        acc.y = fmaxf(acc.y, v.y);
        acc.z = fmaxf(acc.z, v.z);
        acc.w = fmaxf(acc.w, v.w);
    }
    float4 o;
    if (cnt == 0) {
        o = make_float4(0, 0, 0, 0);
    } else {
        float4 dp = g_pos4[gw];
        float4 wx = *(const float4*)(Wp + f);
        float4 wy = *(const float4*)(Wp + 128 + f);
        float4 wz = *(const float4*)(Wp + 256 + f);
        o.x = acc.x - (dp.x * wx.x + dp.y * wy.x + dp.z * wz.x);
        o.y = acc.y - (dp.x * wx.y + dp.y * wy.y + dp.z * wz.y);
        o.z = acc.z - (dp.x * wx.z + dp.y * wy.z + dp.z * wz.z);
        o.w = acc.w - (dp.x * wx.w + dp.y * wy.w + dp.z * wz.w);
    }
    float* oo = phase ? g_agg2 : g_agg1;
    *(float4*)(oo + gw * 128 + f) = o;

    // fused column stats -> 64-way replicated partials
    *(float4*)&shs[w][f] = o;
    float4 q = make_float4(o.x * o.x, o.y * o.y, o.z * o.z, o.w * o.w);
    *(float4*)&shq[w][f] = q;
    __syncthreads();
    int t = threadIdx.x;
    if (t < 128) {
        float a = 0.0f, b = 0.0f;
#pragma unroll
        for (int w2 = 0; w2 < 8; w2++) {
            a += shs[w2][t];
            b += shq[w2][t];
        }
        float* st = g_part + (inst * 64 + (blockIdx.x & 63)) * 256;
        atomicAdd(&st[t], a);
        atomicAdd(&st[128 + t], b);
    }
}

// ---------------- output: relu(BN2(agg2) + BNl(skip)), BN inlined ----------------
__global__ __launch_bounds__(256) void k_out(float* __restrict__ out,
                                             const float* __restrict__ gl,
                                             const float* __restrict__ bel,
                                             const float* __restrict__ g2,
                                             const float* __restrict__ be2) {
    __shared__ float cl[128], hl[128], c2[128], h2[128];
    int t = threadIdx.x;
    if (t < 128) {
        float mu  = g_stat[t] * (1.0f / NN);
        float var = g_stat[128 + t] * (1.0f / NN) - mu * mu;
        float rs  = rsqrtf(var + 1e-5f);
        float s0  = gl[t] * rs;
        cl[t] = s0;
        hl[t] = bel[t] - mu * s0;
    } else {
        int f = t - 128;
        float mu  = g_stat[512 + f] * (1.0f / NN);
        float var = g_stat[512 + 128 + f] * (1.0f / NN) - mu * mu;
        float rs  = rsqrtf(var + 1e-5f);
        float s2  = g2[f] * rs;
        c2[f] = s2;
        h2[f] = be2[f] - mu * s2;
    }
    __syncthreads();
    int i = blockIdx.x * 8 + (t >> 5);
    int f = (t & 31) * 4;
    float4 a  = *(const float4*)(g_agg2 + i * 128 + f);
    float4 s  = *(const float4*)(g_skip + i * 128 + f);
    float4 o;
    o.x = fmaxf(fmaf(a.x, c2[f],     h2[f])     + fmaf(s.x, cl[f],     hl[f]),     0.0f);
    o.y = fmaxf(fmaf(a.y, c2[f + 1], h2[f + 1]) + fmaf(s.y, cl[f + 1], hl[f + 1]), 0.0f);
    o.z = fmaxf(fmaf(a.z, c2[f + 2], h2[f + 2]) + fmaf(s.z, cl[f + 2], hl[f + 2]), 0.0f);
    o.w = fmaxf(fmaf(a.w, c2[f + 3], h2[f + 3]) + fmaf(s.w, cl[f + 3], hl[f + 3]), 0.0f);
    *(float4*)(out + i * 128 + f) = o;
}

// ---------------- launcher ----------------
extern "C" void kernel_launch(void* const* d_in, const int* in_sizes, int n_in,
                              void* d_out, int out_size) {
    const float* x   = (const float*)d_in[0];
    const float* pos = (const float*)d_in[1];
    const int*   ei  = (const int*)  d_in[2];
    const float* W1  = (const float*)d_in[3];
    const float* b1  = (const float*)d_in[4];
    const float* g1  = (const float*)d_in[5];
    const float* be1 = (const float*)d_in[6];
    const float* W2  = (const float*)d_in[7];
    const float* b2  = (const float*)d_in[8];
    const float* g2  = (const float*)d_in[9];
    const float* be2 = (const float*)d_in[10];
    const float* Wl  = (const float*)d_in[11];
    const float* bl  = (const float*)d_in[12];
    const float* gl  = (const float*)d_in[13];
    const float* bel = (const float*)d_in[14];
    float* out = (float*)d_out;

    int gridE = (EE + 255) / 256;
    int gridN = (NN + 255) / 256;
    int gridA = NN / 8;                 // 6250 (8 warps/block, 1 node/warp)
    int smem2 = 4 * 128 * PSTR * 4;     // Ah, Al, Bh, Bl = 139264 bytes

    cudaFuncSetAttribute(k_gemm2_mma, cudaFuncAttributeMaxDynamicSharedMemorySize, smem2);

    k_init<<<gridN, 256>>>(pos);
    k_build<<<gridE, 256>>>(ei);
    k_prepW<<<32, 256>>>(W2);

    k_gemm1<<<(NN + 63) / 64, 256>>>(x, W1, b1, Wl, bl);      // + skip stats (inst 0, replicated)

    k_agg<<<gridA, 256>>>(W1 + 64 * 128, 0, 1);               // + agg1 stats (inst 1, replicated)
    k_red2<<<1, 512>>>(0, 1);                                 // fold partials for inst 0 & 1

    k_gemm2_mma<<<(NN + 127) / 128, 256, smem2>>>(W2, b2, g1, be1);

    k_agg<<<gridA, 256>>>(W2 + 128 * 128, 1, 2);              // + agg2 stats (inst 2, replicated)
    k_red2<<<1, 512>>>(2, -1);                                // fold partials for inst 2

    k_out<<<gridA, 256>>>(out, gl, bel, g2, be2);             // BN0 + BN2 inlined
}

// round 16
// speedup vs baseline: 1.1400x; 1.0280x over previous
#include <cuda_runtime.h>
#include <cuda_bf16.h>
#include <stdint.h>
#include <math.h>

#define NN 50000
#define EE 800000
#define STRIDE 96   // fixed CSR bucket stride; max degree ~45 (Binomial(800k,1/50k))

#define PSTR 68     // padded row stride (words) for K=128 tiles: 64 data + 4 pad (4g+c banks)
#define P1   36     // padded row stride (words) for K=64 tiles: 32 data + 4 pad (same bank map)

// ---------------- scratch (static device globals; no allocs) ----------------
__device__ float    g_z1  [NN * 128];
__device__ float    g_z2  [NN * 128];
__device__ float    g_skip[NN * 128];
__device__ float    g_agg1[NN * 128];
__device__ float    g_agg2[NN * 128];
__device__ float4   g_pos4[NN];
__device__ int      g_deg [NN];
__device__ __align__(16) int g_csr [NN * STRIDE];
__device__ float    g_part[3 * 64 * 256];  // 64-way replicated [inst][rep]{sum[128],sumsq[128]}
__device__ float    g_stat[3 * 256];
__device__ __align__(16) uint32_t g_bh [128 * PSTR];      // W2^T bf16 hi
__device__ __align__(16) uint32_t g_bl [128 * PSTR];      // W2^T bf16 lo
__device__ __align__(16) uint32_t g_B1h[2 * 128 * P1];    // [y][n][kp]: y=0 W1a^T, y=1 Wl^T (hi)
__device__ __align__(16) uint32_t g_B1l[2 * 128 * P1];    // (lo)

// ---------------- bf16 mma.sync m16n8k16 ----------------
__device__ __forceinline__ void mma_bf16(float& c0, float& c1, float& c2, float& c3,
                                         uint32_t a0, uint32_t a1, uint32_t a2, uint32_t a3,
                                         uint32_t b0, uint32_t b1) {
    asm volatile(
        "mma.sync.aligned.m16n8k16.row.col.f32.bf16.bf16.f32 "
        "{%0,%1,%2,%3}, {%4,%5,%6,%7}, {%8,%9}, {%0,%1,%2,%3};"
        : "+f"(c0), "+f"(c1), "+f"(c2), "+f"(c3)
        : "r"(a0), "r"(a1), "r"(a2), "r"(a3), "r"(b0), "r"(b1));
}
__device__ __forceinline__ uint32_t pack_bf16x2(float lo, float hi) {
    __nv_bfloat162 h;
    h.x = __float2bfloat16(lo);
    h.y = __float2bfloat16(hi);
    return *(uint32_t*)&h;
}

// ---------------- init + pack pos ----------------
__global__ void k_init(const float* __restrict__ pos) {
    int i = blockIdx.x * 256 + threadIdx.x;
    if (i < NN) {
        g_deg[i] = 0;
        g_pos4[i] = make_float4(pos[i * 3], pos[i * 3 + 1], pos[i * 3 + 2], 0.0f);
    }
    if (i < 3 * 64 * 256) g_part[i] = 0.0f;
}

// ---------------- one-pass CSR build ----------------
__global__ void k_build(const int* __restrict__ ei) {
    int e = blockIdx.x * 256 + threadIdx.x;
    if (e < EE) {
        int s = ei[e];
        int d = ei[EE + e];
        int p = atomicAdd(&g_deg[d], 1);
        g_csr[d * STRIDE + p] = s;
    }
}

// ---------------- weight prep: W2 (K=128) + W1a/Wl (K=64) transposed bf16 hi/lo ----------------
__global__ void k_prep(const float* __restrict__ W1, const float* __restrict__ Wl,
                       const float* __restrict__ W2) {
    int idx = blockIdx.x * 256 + threadIdx.x;
    if (idx < 128 * 64) {                   // W2: n in 0..127, kp in 0..63
        int n = idx >> 6, kp = idx & 63, k = kp * 2;
        float v0 = W2[k * 128 + n];
        float v1 = W2[(k + 1) * 128 + n];
        __nv_bfloat16 h0 = __float2bfloat16(v0);
        __nv_bfloat16 h1 = __float2bfloat16(v1);
        __nv_bfloat162 hh; hh.x = h0; hh.y = h1;
        g_bh[n * PSTR + kp] = *(uint32_t*)&hh;
        g_bl[n * PSTR + kp] = pack_bf16x2(v0 - __bfloat162float(h0), v1 - __bfloat162float(h1));
    } else if (idx < 128 * 64 + 2 * 128 * 32) {   // W1a / Wl: 4096 each
        int j = idx - 128 * 64;
        int y = j >> 12;
        int r = j & 4095;
        int n = r >> 5, kp = r & 31, k = kp * 2;
        const float* W = y ? Wl : W1;
        float v0 = W[k * 128 + n];
        float v1 = W[(k + 1) * 128 + n];
        __nv_bfloat16 h0 = __float2bfloat16(v0);
        __nv_bfloat16 h1 = __float2bfloat16(v1);
        __nv_bfloat162 hh; hh.x = h0; hh.y = h1;
        g_B1h[y * 128 * P1 + n * P1 + kp] = *(uint32_t*)&hh;
        g_B1l[y * 128 * P1 + n * P1 + kp] = pack_bf16x2(v0 - __bfloat162float(h0), v1 - __bfloat162float(h1));
    }
}

// ---------------- reduce 64 replicated partials -> g_stat ----------------
__global__ void k_red2(int ia, int ib) {
    int t = threadIdx.x;                 // 512 threads
    int inst = (t < 256) ? ia : ib;
    int c = t & 255;
    if (inst < 0) return;
    const float* p = g_part + inst * 64 * 256 + c;
    float s = 0.0f;
#pragma unroll
    for (int r = 0; r < 64; r++) s += p[r * 256];
    g_stat[inst * 256 + c] = s;
}

// ---------------- GEMM1 (mma.sync): y=0 -> z1 = x@W1a + b1 + pos@Wp1 ; y=1 -> skip = x@Wl + bl (+stats) ----------------
__global__ __launch_bounds__(256, 1) void k_gemm1_mma(const float* __restrict__ x,
                                                      const float* __restrict__ W1,
                                                      const float* __restrict__ b1,
                                                      const float* __restrict__ bl) {
    extern __shared__ uint32_t sm[];
    uint32_t* Ah = sm;                   // [128][P1]
    uint32_t* Al = Ah + 128 * P1;
    uint32_t* Bh = Al + 128 * P1;
    uint32_t* Bl = Bh + 128 * P1;
    __shared__ float s_bias[128], s_wx[128], s_wy[128], s_wz[128];

    int t = threadIdx.x;
    int m0 = blockIdx.x * 128;
    int y  = blockIdx.y;                 // 0: z1, 1: skip
    int lane = t & 31, wid = t >> 5;
    int g = lane >> 2, qc = lane & 3;

    if (t < 128) {
        if (y == 0) {
            const float* Wp = W1 + 64 * 128;
            s_bias[t] = b1[t];
            s_wx[t] = Wp[t];
            s_wy[t] = Wp[128 + t];
            s_wz[t] = Wp[256 + t];
        } else {
            s_bias[t] = bl[t];
        }
    }
    // copy B image
    {
        const uint4* srcH = (const uint4*)(g_B1h + y * 128 * P1);
        const uint4* srcL = (const uint4*)(g_B1l + y * 128 * P1);
        uint4* dstH = (uint4*)Bh;
        uint4* dstL = (uint4*)Bl;
        for (int i = t; i < 128 * P1 / 4; i += 256) {
            dstH[i] = srcH[i];
            dstL[i] = srcL[i];
        }
    }
    // convert A tile: x rows, split bf16 hi/lo
    for (int idx = t; idx < 128 * 32; idx += 256) {
        int row = idx >> 5, kp = idx & 31, k = kp * 2;
        int grow = m0 + row;
        float2 v = make_float2(0.0f, 0.0f);
        if (grow < NN) v = *(const float2*)(x + grow * 64 + k);
        __nv_bfloat16 h0 = __float2bfloat16(v.x);
        __nv_bfloat16 h1 = __float2bfloat16(v.y);
        __nv_bfloat162 hh; hh.x = h0; hh.y = h1;
        Ah[row * P1 + kp] = *(uint32_t*)&hh;
        Al[row * P1 + kp] = pack_bf16x2(v.x - __bfloat162float(h0), v.y - __bfloat162float(h1));
    }
    __syncthreads();

    int warpM = wid & 3, warpN = wid >> 2;
    int rbase = warpM * 32;
    int nbase = warpN * 64;

    float acc[2][8][4];
#pragma unroll
    for (int mi = 0; mi < 2; mi++)
#pragma unroll
        for (int ni = 0; ni < 8; ni++)
#pragma unroll
            for (int j = 0; j < 4; j++) acc[mi][ni][j] = 0.0f;

#pragma unroll
    for (int k0 = 0; k0 < 4; k0++) {
        int kw = k0 * 8 + qc;
        uint32_t ah[2][4];
#pragma unroll
        for (int mi = 0; mi < 2; mi++) {
            int r = rbase + mi * 16 + g;
            ah[mi][0] = Ah[r * P1 + kw];
            ah[mi][1] = Ah[(r + 8) * P1 + kw];
            ah[mi][2] = Ah[r * P1 + kw + 4];
            ah[mi][3] = Ah[(r + 8) * P1 + kw + 4];
        }
        uint32_t bh[8][2];
#pragma unroll
        for (int ni = 0; ni < 8; ni++) {
            int n = nbase + ni * 8 + g;
            bh[ni][0] = Bh[n * P1 + kw];
            bh[ni][1] = Bh[n * P1 + kw + 4];
        }
#pragma unroll
        for (int mi = 0; mi < 2; mi++)
#pragma unroll
            for (int ni = 0; ni < 8; ni++)
                mma_bf16(acc[mi][ni][0], acc[mi][ni][1], acc[mi][ni][2], acc[mi][ni][3],
                         ah[mi][0], ah[mi][1], ah[mi][2], ah[mi][3], bh[ni][0], bh[ni][1]);
#pragma unroll
        for (int mi = 0; mi < 2; mi++) {
            int r = rbase + mi * 16 + g;
            uint32_t al0 = Al[r * P1 + kw];
            uint32_t al1 = Al[(r + 8) * P1 + kw];
            uint32_t al2 = Al[r * P1 + kw + 4];
            uint32_t al3 = Al[(r + 8) * P1 + kw + 4];
#pragma unroll
            for (int ni = 0; ni < 8; ni++)
                mma_bf16(acc[mi][ni][0], acc[mi][ni][1], acc[mi][ni][2], acc[mi][ni][3],
                         al0, al1, al2, al3, bh[ni][0], bh[ni][1]);
        }
#pragma unroll
        for (int ni = 0; ni < 8; ni++) {
            int n = nbase + ni * 8 + g;
            uint32_t bl0 = Bl[n * P1 + kw];
            uint32_t bl1 = Bl[n * P1 + kw + 4];
#pragma unroll
            for (int mi = 0; mi < 2; mi++)
                mma_bf16(acc[mi][ni][0], acc[mi][ni][1], acc[mi][ni][2], acc[mi][ni][3],
                         ah[mi][0], ah[mi][1], ah[mi][2], ah[mi][3], bl0, bl1);
        }
    }

    if (y == 0) {
        // z1 epilogue: + b1 + pos@Wp1
#pragma unroll
        for (int mi = 0; mi < 2; mi++) {
            int r0 = m0 + rbase + mi * 16 + g;
            int r1 = r0 + 8;
            bool v0 = r0 < NN, v1 = r1 < NN;
            float4 p0 = g_pos4[v0 ? r0 : 0];
            float4 p1 = g_pos4[v1 ? r1 : 0];
#pragma unroll
            for (int ni = 0; ni < 8; ni++) {
                int c = nbase + ni * 8 + qc * 2;
                float bx0 = s_bias[c]     + p0.x * s_wx[c]     + p0.y * s_wy[c]     + p0.z * s_wz[c];
                float bx1 = s_bias[c + 1] + p0.x * s_wx[c + 1] + p0.y * s_wy[c + 1] + p0.z * s_wz[c + 1];
                float by0 = s_bias[c]     + p1.x * s_wx[c]     + p1.y * s_wy[c]     + p1.z * s_wz[c];
                float by1 = s_bias[c + 1] + p1.x * s_wx[c + 1] + p1.y * s_wy[c + 1] + p1.z * s_wz[c + 1];
                if (v0) *(float2*)(g_z1 + r0 * 128 + c) = make_float2(acc[mi][ni][0] + bx0, acc[mi][ni][1] + bx1);
                if (v1) *(float2*)(g_z1 + r1 * 128 + c) = make_float2(acc[mi][ni][2] + by0, acc[mi][ni][3] + by1);
            }
        }
    } else {
        // skip epilogue: + bl, store, fused stats (butterfly over g-lanes, diluted atomics)
        float scol[8][2], qcol[8][2];
#pragma unroll
        for (int ni = 0; ni < 8; ni++) {
            scol[ni][0] = 0.0f; scol[ni][1] = 0.0f;
            qcol[ni][0] = 0.0f; qcol[ni][1] = 0.0f;
        }
#pragma unroll
        for (int mi = 0; mi < 2; mi++) {
            int r0 = m0 + rbase + mi * 16 + g;
            int r1 = r0 + 8;
            bool v0 = r0 < NN, v1 = r1 < NN;
#pragma unroll
            for (int ni = 0; ni < 8; ni++) {
                int c = nbase + ni * 8 + qc * 2;
                float s00 = acc[mi][ni][0] + s_bias[c];
                float s01 = acc[mi][ni][1] + s_bias[c + 1];
                float s10 = acc[mi][ni][2] + s_bias[c];
                float s11 = acc[mi][ni][3] + s_bias[c + 1];
                if (v0) {
                    *(float2*)(g_skip + r0 * 128 + c) = make_float2(s00, s01);
                    scol[ni][0] += s00; qcol[ni][0] += s00 * s00;
                    scol[ni][1] += s01; qcol[ni][1] += s01 * s01;
                }
                if (v1) {
                    *(float2*)(g_skip + r1 * 128 + c) = make_float2(s10, s11);
                    scol[ni][0] += s10; qcol[ni][0] += s10 * s10;
                    scol[ni][1] += s11; qcol[ni][1] += s11 * s11;
                }
            }
        }
#pragma unroll
        for (int m = 4; m <= 16; m <<= 1) {
#pragma unroll
            for (int ni = 0; ni < 8; ni++) {
                scol[ni][0] += __shfl_xor_sync(0xffffffffu, scol[ni][0], m);
                scol[ni][1] += __shfl_xor_sync(0xffffffffu, scol[ni][1], m);
                qcol[ni][0] += __shfl_xor_sync(0xffffffffu, qcol[ni][0], m);
                qcol[ni][1] += __shfl_xor_sync(0xffffffffu, qcol[ni][1], m);
            }
        }
        if (g == 0) {
            float* st = g_part + (blockIdx.x & 63) * 256;   // inst 0
#pragma unroll
            for (int ni = 0; ni < 8; ni++) {
                int c = nbase + ni * 8 + qc * 2;
                atomicAdd(&st[c],           scol[ni][0]);
                atomicAdd(&st[c + 1],       scol[ni][1]);
                atomicAdd(&st[128 + c],     qcol[ni][0]);
                atomicAdd(&st[128 + c + 1], qcol[ni][1]);
            }
        }
    }
}

// ---------------- GEMM2 (mma.sync bf16 3-term split): z2 = relu(BN1(agg1))@W2a + b2 + pos@Wp2 ----------------
__global__ __launch_bounds__(256, 1) void k_gemm2_mma(const float* __restrict__ W2,
                                                      const float* __restrict__ b2,
                                                      const float* __restrict__ g1,
                                                      const float* __restrict__ be1) {
    extern __shared__ uint32_t sm[];
    uint32_t* Ah = sm;                   // [128][PSTR]
    uint32_t* Al = Ah + 128 * PSTR;
    uint32_t* Bh = Al + 128 * PSTR;
    uint32_t* Bl = Bh + 128 * PSTR;
    __shared__ float sc[128], sf[128];
    __shared__ float s_bias[128], s_wx[128], s_wy[128], s_wz[128];

    int t = threadIdx.x;
    int m0 = blockIdx.x * 128;
    int lane = t & 31, wid = t >> 5;
    int g = lane >> 2, qc = lane & 3;

    if (t < 128) {
        float mu  = g_stat[256 + t] * (1.0f / NN);
        float var = g_stat[256 + 128 + t] * (1.0f / NN) - mu * mu;
        float rs  = rsqrtf(var + 1e-5f);
        float scale = g1[t] * rs;
        sc[t] = scale;
        sf[t] = be1[t] - mu * scale;
        const float* Wp = W2 + 128 * 128;
        s_bias[t] = b2[t];
        s_wx[t] = Wp[t];
        s_wy[t] = Wp[128 + t];
        s_wz[t] = Wp[256 + t];
    }
    {
        const uint4* srcH = (const uint4*)g_bh;
        const uint4* srcL = (const uint4*)g_bl;
        uint4* dstH = (uint4*)Bh;
        uint4* dstL = (uint4*)Bl;
        for (int i = t; i < 128 * PSTR / 4; i += 256) {
            dstH[i] = srcH[i];
            dstL[i] = srcL[i];
        }
    }
    __syncthreads();

    for (int idx = t; idx < 128 * 64; idx += 256) {
        int row = idx >> 6, kp = idx & 63, k = kp * 2;
        int grow = m0 + row;
        float2 v = make_float2(0.0f, 0.0f);
        if (grow < NN) v = *(const float2*)(g_agg1 + grow * 128 + k);
        float a0 = fmaxf(fmaf(v.x, sc[k],     sf[k]),     0.0f);
        float a1 = fmaxf(fmaf(v.y, sc[k + 1], sf[k + 1]), 0.0f);
        __nv_bfloat16 h0 = __float2bfloat16(a0);
        __nv_bfloat16 h1 = __float2bfloat16(a1);
        __nv_bfloat162 hh; hh.x = h0; hh.y = h1;
        Ah[row * PSTR + kp] = *(uint32_t*)&hh;
        Al[row * PSTR + kp] = pack_bf16x2(a0 - __bfloat162float(h0), a1 - __bfloat162float(h1));
    }
    __syncthreads();

    int warpM = wid & 3, warpN = wid >> 2;
    int rbase = warpM * 32;
    int nbase = warpN * 64;

    float acc[2][8][4];
#pragma unroll
    for (int mi = 0; mi < 2; mi++)
#pragma unroll
        for (int ni = 0; ni < 8; ni++)
#pragma unroll
            for (int j = 0; j < 4; j++) acc[mi][ni][j] = 0.0f;

#pragma unroll
    for (int k0 = 0; k0 < 8; k0++) {
        int kw = k0 * 8 + qc;
        uint32_t ah[2][4];
#pragma unroll
        for (int mi = 0; mi < 2; mi++) {
            int r = rbase + mi * 16 + g;
            ah[mi][0] = Ah[r * PSTR + kw];
            ah[mi][1] = Ah[(r + 8) * PSTR + kw];
            ah[mi][2] = Ah[r * PSTR + kw + 4];
            ah[mi][3] = Ah[(r + 8) * PSTR + kw + 4];
        }
        uint32_t bh[8][2];
#pragma unroll
        for (int ni = 0; ni < 8; ni++) {
            int n = nbase + ni * 8 + g;
            bh[ni][0] = Bh[n * PSTR + kw];
            bh[ni][1] = Bh[n * PSTR + kw + 4];
        }
#pragma unroll
        for (int mi = 0; mi < 2; mi++)
#pragma unroll
            for (int ni = 0; ni < 8; ni++)
                mma_bf16(acc[mi][ni][0], acc[mi][ni][1], acc[mi][ni][2], acc[mi][ni][3],
                         ah[mi][0], ah[mi][1], ah[mi][2], ah[mi][3], bh[ni][0], bh[ni][1]);
#pragma unroll
        for (int mi = 0; mi < 2; mi++) {
            int r = rbase + mi * 16 + g;
            uint32_t al0 = Al[r * PSTR + kw];
            uint32_t al1 = Al[(r + 8) * PSTR + kw];
            uint32_t al2 = Al[r * PSTR + kw + 4];
            uint32_t al3 = Al[(r + 8) * PSTR + kw + 4];
#pragma unroll
            for (int ni = 0; ni < 8; ni++)
                mma_bf16(acc[mi][ni][0], acc[mi][ni][1], acc[mi][ni][2], acc[mi][ni][3],
                         al0, al1, al2, al3, bh[ni][0], bh[ni][1]);
        }
#pragma unroll
        for (int ni = 0; ni < 8; ni++) {
            int n = nbase + ni * 8 + g;
            uint32_t bl0 = Bl[n * PSTR + kw];
            uint32_t bl1 = Bl[n * PSTR + kw + 4];
#pragma unroll
            for (int mi = 0; mi < 2; mi++)
                mma_bf16(acc[mi][ni][0], acc[mi][ni][1], acc[mi][ni][2], acc[mi][ni][3],
                         ah[mi][0], ah[mi][1], ah[mi][2], ah[mi][3], bl0, bl1);
        }
    }

#pragma unroll
    for (int mi = 0; mi < 2; mi++) {
        int r0 = m0 + rbase + mi * 16 + g;
        int r1 = r0 + 8;
        bool v0 = r0 < NN, v1 = r1 < NN;
        float4 p0 = g_pos4[v0 ? r0 : 0];
        float4 p1 = g_pos4[v1 ? r1 : 0];
#pragma unroll
        for (int ni = 0; ni < 8; ni++) {
            int c = nbase + ni * 8 + qc * 2;
            float bx0 = s_bias[c]     + p0.x * s_wx[c]     + p0.y * s_wy[c]     + p0.z * s_wz[c];
            float bx1 = s_bias[c + 1] + p0.x * s_wx[c + 1] + p0.y * s_wy[c + 1] + p0.z * s_wz[c + 1];
            float by0 = s_bias[c]     + p1.x * s_wx[c]     + p1.y * s_wy[c]     + p1.z * s_wz[c];
            float by1 = s_bias[c + 1] + p1.x * s_wx[c + 1] + p1.y * s_wy[c + 1] + p1.z * s_wz[c + 1];
            if (v0) *(float2*)(g_z2 + r0 * 128 + c) = make_float2(acc[mi][ni][0] + bx0, acc[mi][ni][1] + bx1);
            if (v1) *(float2*)(g_z2 + r1 * 128 + c) = make_float2(acc[mi][ni][2] + by0, acc[mi][ni][3] + by1);
        }
    }
}

// ---------------- aggregation: one warp per dst, gather+max, diluted stats ----------------
__global__ __launch_bounds__(256) void k_agg(const float* __restrict__ Wp, int phase, int inst) {
    __shared__ float shs[8][128];
    __shared__ float shq[8][128];
    int w    = threadIdx.x >> 5;
    int gw   = blockIdx.x * 8 + w;
    int lane = threadIdx.x & 31;
    int f = lane * 4;
    const float* __restrict__ z = phase ? g_z2 : g_z1;
    int cnt = g_deg[gw];
    const int* __restrict__ bucket = g_csr + gw * STRIDE;
    float ninf = __int_as_float(0xff800000);
    float4 acc = make_float4(ninf, ninf, ninf, ninf);
#pragma unroll 8
    for (int e = 0; e < cnt; e++) {
        int s = __ldg(&bucket[e]);
        float4 v = *(const float4*)(z + s * 128 + f);
        acc.x = fmaxf(acc.x, v.x);
        acc.y = fmaxf(acc.y, v.y);
        acc.z = fmaxf(acc.z, v.z);
        acc.w = fmaxf(acc.w, v.w);
    }
    float4 o;
    if (cnt == 0) {
        o = make_float4(0, 0, 0, 0);
    } else {
        float4 dp = g_pos4[gw];
        float4 wx = *(const float4*)(Wp + f);
        float4 wy = *(const float4*)(Wp + 128 + f);
        float4 wz = *(const float4*)(Wp + 256 + f);
        o.x = acc.x - (dp.x * wx.x + dp.y * wy.x + dp.z * wz.x);
        o.y = acc.y - (dp.x * wx.y + dp.y * wy.y + dp.z * wz.y);
        o.z = acc.z - (dp.x * wx.z + dp.y * wy.z + dp.z * wz.z);
        o.w = acc.w - (dp.x * wx.w + dp.y * wy.w + dp.z * wz.w);
    }
    float* oo = phase ? g_agg2 : g_agg1;
    *(float4*)(oo + gw * 128 + f) = o;

    *(float4*)&shs[w][f] = o;
    float4 q = make_float4(o.x * o.x, o.y * o.y, o.z * o.z, o.w * o.w);
    *(float4*)&shq[w][f] = q;
    __syncthreads();
    int t = threadIdx.x;
    if (t < 128) {
        float a = 0.0f, b = 0.0f;
#pragma unroll
        for (int w2 = 0; w2 < 8; w2++) {
            a += shs[w2][t];
            b += shq[w2][t];
        }
        float* st = g_part + (inst * 64 + (blockIdx.x & 63)) * 256;
        atomicAdd(&st[t], a);
        atomicAdd(&st[128 + t], b);
    }
}

// ---------------- output: relu(BN2(agg2) + BNl(skip)), BN inlined ----------------
__global__ __launch_bounds__(256) void k_out(float* __restrict__ out,
                                             const float* __restrict__ gl,
                                             const float* __restrict__ bel,
                                             const float* __restrict__ g2,
                                             const float* __restrict__ be2) {
    __shared__ float cl[128], hl[128], c2[128], h2[128];
    int t = threadIdx.x;
    if (t < 128) {
        float mu  = g_stat[t] * (1.0f / NN);
        float var = g_stat[128 + t] * (1.0f / NN) - mu * mu;
        float rs  = rsqrtf(var + 1e-5f);
        float s0  = gl[t] * rs;
        cl[t] = s0;
        hl[t] = bel[t] - mu * s0;
    } else {
        int f = t - 128;
        float mu  = g_stat[512 + f] * (1.0f / NN);
        float var = g_stat[512 + 128 + f] * (1.0f / NN) - mu * mu;
        float rs  = rsqrtf(var + 1e-5f);
        float s2  = g2[f] * rs;
        c2[f] = s2;
        h2[f] = be2[f] - mu * s2;
    }
    __syncthreads();
    int i = blockIdx.x * 8 + (t >> 5);
    int f = (t & 31) * 4;
    float4 a  = *(const float4*)(g_agg2 + i * 128 + f);
    float4 s  = *(const float4*)(g_skip + i * 128 + f);
    float4 o;
    o.x = fmaxf(fmaf(a.x, c2[f],     h2[f])     + fmaf(s.x, cl[f],     hl[f]),     0.0f);
    o.y = fmaxf(fmaf(a.y, c2[f + 1], h2[f + 1]) + fmaf(s.y, cl[f + 1], hl[f + 1]), 0.0f);
    o.z = fmaxf(fmaf(a.z, c2[f + 2], h2[f + 2]) + fmaf(s.z, cl[f + 2], hl[f + 2]), 0.0f);
    o.w = fmaxf(fmaf(a.w, c2[f + 3], h2[f + 3]) + fmaf(s.w, cl[f + 3], hl[f + 3]), 0.0f);
    *(float4*)(out + i * 128 + f) = o;
}

// ---------------- launcher ----------------
extern "C" void kernel_launch(void* const* d_in, const int* in_sizes, int n_in,
                              void* d_out, int out_size) {
    const float* x   = (const float*)d_in[0];
    const float* pos = (const float*)d_in[1];
    const int*   ei  = (const int*)  d_in[2];
    const float* W1  = (const float*)d_in[3];
    const float* b1  = (const float*)d_in[4];
    const float* g1  = (const float*)d_in[5];
    const float* be1 = (const float*)d_in[6];
    const float* W2  = (const float*)d_in[7];
    const float* b2  = (const float*)d_in[8];
    const float* g2  = (const float*)d_in[9];
    const float* be2 = (const float*)d_in[10];
    const float* Wl  = (const float*)d_in[11];
    const float* bl  = (const float*)d_in[12];
    const float* gl  = (const float*)d_in[13];
    const float* bel = (const float*)d_in[14];
    float* out = (float*)d_out;

    int gridE = (EE + 255) / 256;
    int gridN = (NN + 255) / 256;
    int gridA = NN / 8;                       // 6250
    int gridM = (NN + 127) / 128;             // 391
    int smem1 = 4 * 128 * P1 * 4;             // 73728
    int smem2 = 4 * 128 * PSTR * 4;           // 139264

    cudaFuncSetAttribute(k_gemm1_mma, cudaFuncAttributeMaxDynamicSharedMemorySize, smem1);
    cudaFuncSetAttribute(k_gemm2_mma, cudaFuncAttributeMaxDynamicSharedMemorySize, smem2);

    k_init<<<gridN, 256>>>(pos);
    k_build<<<gridE, 256>>>(ei);
    k_prep<<<64, 256>>>(W1, Wl, W2);

    k_gemm1_mma<<<dim3(gridM, 2), 256, smem1>>>(x, W1, b1, bl);   // + skip stats (inst 0)

    k_agg<<<gridA, 256>>>(W1 + 64 * 128, 0, 1);                   // + agg1 stats (inst 1)
    k_red2<<<1, 512>>>(0, 1);

    k_gemm2_mma<<<gridM, 256, smem2>>>(W2, b2, g1, be1);

    k_agg<<<gridA, 256>>>(W2 + 128 * 128, 1, 2);                  // + agg2 stats (inst 2)
    k_red2<<<1, 512>>>(2, -1);

    k_out<<<gridA, 256>>>(out, gl, bel, g2, be2);
}

// round 17
// speedup vs baseline: 1.3405x; 1.1758x over previous
#include <cuda_runtime.h>
#include <cuda_bf16.h>
#include <stdint.h>
#include <math.h>

#define NN 50000
#define EE 800000
#define STRIDE 96   // fixed CSR bucket stride; max degree ~45 (Binomial(800k,1/50k))

#define PSTR 68     // padded row stride (words) for K=128 tiles
#define P1   36     // padded row stride (words) for K=64 tiles

// ---------------- scratch (static device globals; no allocs) ----------------
__device__ float    g_z1  [NN * 128];
__device__ float    g_z2  [NN * 128];
__device__ float    g_skip[NN * 128];
__device__ float    g_agg1[NN * 128];
__device__ float    g_agg2[NN * 128];
__device__ float4   g_pos4[NN];
__device__ int      g_deg [NN];
__device__ __align__(16) int g_csr [NN * STRIDE];
__device__ float    g_part[3 * 64 * 256];
__device__ float    g_stat[3 * 256];
__device__ __align__(16) uint32_t g_bh [128 * PSTR];      // W2^T bf16 hi
__device__ __align__(16) uint32_t g_bl [128 * PSTR];      // W2^T bf16 lo
__device__ __align__(16) uint32_t g_B1h[2 * 128 * P1];    // [y][n][kp]: y=0 W1a^T, y=1 Wl^T (hi)
__device__ __align__(16) uint32_t g_B1l[2 * 128 * P1];    // (lo)

// ---------------- bf16 mma.sync m16n8k16 ----------------
__device__ __forceinline__ void mma_bf16(float& c0, float& c1, float& c2, float& c3,
                                         uint32_t a0, uint32_t a1, uint32_t a2, uint32_t a3,
                                         uint32_t b0, uint32_t b1) {
    asm volatile(
        "mma.sync.aligned.m16n8k16.row.col.f32.bf16.bf16.f32 "
        "{%0,%1,%2,%3}, {%4,%5,%6,%7}, {%8,%9}, {%0,%1,%2,%3};"
        : "+f"(c0), "+f"(c1), "+f"(c2), "+f"(c3)
        : "r"(a0), "r"(a1), "r"(a2), "r"(a3), "r"(b0), "r"(b1));
}
__device__ __forceinline__ uint32_t pack_bf16x2(float lo, float hi) {
    __nv_bfloat162 h;
    h.x = __float2bfloat16(lo);
    h.y = __float2bfloat16(hi);
    return *(uint32_t*)&h;
}

// ---------------- init + pack pos ----------------
__global__ void k_init(const float* __restrict__ pos) {
    int i = blockIdx.x * 256 + threadIdx.x;
    if (i < NN) {
        g_deg[i] = 0;
        g_pos4[i] = make_float4(pos[i * 3], pos[i * 3 + 1], pos[i * 3 + 2], 0.0f);
    }
    if (i < 3 * 64 * 256) g_part[i] = 0.0f;
}

// ---------------- one-pass CSR build ----------------
__global__ void k_build(const int* __restrict__ ei) {
    int e = blockIdx.x * 256 + threadIdx.x;
    if (e < EE) {
        int s = ei[e];
        int d = ei[EE + e];
        int p = atomicAdd(&g_deg[d], 1);
        g_csr[d * STRIDE + p] = s;
    }
}

// ---------------- weight prep ----------------
__global__ void k_prep(const float* __restrict__ W1, const float* __restrict__ Wl,
                       const float* __restrict__ W2) {
    int idx = blockIdx.x * 256 + threadIdx.x;
    if (idx < 128 * 64) {
        int n = idx >> 6, kp = idx & 63, k = kp * 2;
        float v0 = W2[k * 128 + n];
        float v1 = W2[(k + 1) * 128 + n];
        __nv_bfloat16 h0 = __float2bfloat16(v0);
        __nv_bfloat16 h1 = __float2bfloat16(v1);
        __nv_bfloat162 hh; hh.x = h0; hh.y = h1;
        g_bh[n * PSTR + kp] = *(uint32_t*)&hh;
        g_bl[n * PSTR + kp] = pack_bf16x2(v0 - __bfloat162float(h0), v1 - __bfloat162float(h1));
    } else if (idx < 128 * 64 + 2 * 128 * 32) {
        int j = idx - 128 * 64;
        int y = j >> 12;
        int r = j & 4095;
        int n = r >> 5, kp = r & 31, k = kp * 2;
        const float* W = y ? Wl : W1;
        float v0 = W[k * 128 + n];
        float v1 = W[(k + 1) * 128 + n];
        __nv_bfloat16 h0 = __float2bfloat16(v0);
        __nv_bfloat16 h1 = __float2bfloat16(v1);
        __nv_bfloat162 hh; hh.x = h0; hh.y = h1;
        g_B1h[y * 128 * P1 + n * P1 + kp] = *(uint32_t*)&hh;
        g_B1l[y * 128 * P1 + n * P1 + kp] = pack_bf16x2(v0 - __bfloat162float(h0), v1 - __bfloat162float(h1));
    }
}

// ---------------- reduce partials ----------------
__global__ void k_red2(int ia, int ib) {
    int t = threadIdx.x;
    int inst = (t < 256) ? ia : ib;
    int c = t & 255;
    if (inst < 0) return;
    const float* p = g_part + inst * 64 * 256 + c;
    float s = 0.0f;
#pragma unroll
    for (int r = 0; r < 64; r++) s += p[r * 256];
    g_stat[inst * 256 + c] = s;
}

// ---------------- GEMM1 (mma.sync, 2 blk/SM): y=0 -> z1 ; y=1 -> skip (+stats) ----------------
__global__ __launch_bounds__(256, 2) void k_gemm1_mma(const float* __restrict__ x,
                                                      const float* __restrict__ W1,
                                                      const float* __restrict__ b1,
                                                      const float* __restrict__ bl) {
    extern __shared__ uint32_t sm[];
    uint32_t* Ah = sm;                   // [128][P1]
    uint32_t* Al = Ah + 128 * P1;
    uint32_t* Bh = Al + 128 * P1;
    uint32_t* Bl = Bh + 128 * P1;
    __shared__ float s_bias[128], s_wx[128], s_wy[128], s_wz[128];

    int t = threadIdx.x;
    int m0 = blockIdx.x * 128;
    int y  = blockIdx.y;
    int lane = t & 31, wid = t >> 5;
    int g = lane >> 2, qc = lane & 3;

    if (t < 128) {
        if (y == 0) {
            const float* Wp = W1 + 64 * 128;
            s_bias[t] = b1[t];
            s_wx[t] = Wp[t];
            s_wy[t] = Wp[128 + t];
            s_wz[t] = Wp[256 + t];
        } else {
            s_bias[t] = bl[t];
        }
    }
    {
        const uint4* srcH = (const uint4*)(g_B1h + y * 128 * P1);
        const uint4* srcL = (const uint4*)(g_B1l + y * 128 * P1);
        uint4* dstH = (uint4*)Bh;
        uint4* dstL = (uint4*)Bl;
        for (int i = t; i < 128 * P1 / 4; i += 256) {
            dstH[i] = srcH[i];
            dstL[i] = srcL[i];
        }
    }
    for (int idx = t; idx < 128 * 32; idx += 256) {
        int row = idx >> 5, kp = idx & 31, k = kp * 2;
        int grow = m0 + row;
        float2 v = make_float2(0.0f, 0.0f);
        if (grow < NN) v = *(const float2*)(x + grow * 64 + k);
        __nv_bfloat16 h0 = __float2bfloat16(v.x);
        __nv_bfloat16 h1 = __float2bfloat16(v.y);
        __nv_bfloat162 hh; hh.x = h0; hh.y = h1;
        Ah[row * P1 + kp] = *(uint32_t*)&hh;
        Al[row * P1 + kp] = pack_bf16x2(v.x - __bfloat162float(h0), v.y - __bfloat162float(h1));
    }
    __syncthreads();

    int warpM = wid & 3, warpN = wid >> 2;
    int rbase = warpM * 32;
    int nbase = warpN * 64;

    float acc[2][8][4];
#pragma unroll
    for (int mi = 0; mi < 2; mi++)
#pragma unroll
        for (int ni = 0; ni < 8; ni++)
#pragma unroll
            for (int j = 0; j < 4; j++) acc[mi][ni][j] = 0.0f;

#pragma unroll
    for (int k0 = 0; k0 < 4; k0++) {
        int kw = k0 * 8 + qc;
        uint32_t ah[2][4];
#pragma unroll
        for (int mi = 0; mi < 2; mi++) {
            int r = rbase + mi * 16 + g;
            ah[mi][0] = Ah[r * P1 + kw];
            ah[mi][1] = Ah[(r + 8) * P1 + kw];
            ah[mi][2] = Ah[r * P1 + kw + 4];
            ah[mi][3] = Ah[(r + 8) * P1 + kw + 4];
        }
        uint32_t bh[8][2];
#pragma unroll
        for (int ni = 0; ni < 8; ni++) {
            int n = nbase + ni * 8 + g;
            bh[ni][0] = Bh[n * P1 + kw];
            bh[ni][1] = Bh[n * P1 + kw + 4];
        }
#pragma unroll
        for (int mi = 0; mi < 2; mi++)
#pragma unroll
            for (int ni = 0; ni < 8; ni++)
                mma_bf16(acc[mi][ni][0], acc[mi][ni][1], acc[mi][ni][2], acc[mi][ni][3],
                         ah[mi][0], ah[mi][1], ah[mi][2], ah[mi][3], bh[ni][0], bh[ni][1]);
#pragma unroll
        for (int mi = 0; mi < 2; mi++) {
            int r = rbase + mi * 16 + g;
            uint32_t al0 = Al[r * P1 + kw];
            uint32_t al1 = Al[(r + 8) * P1 + kw];
            uint32_t al2 = Al[r * P1 + kw + 4];
            uint32_t al3 = Al[(r + 8) * P1 + kw + 4];
#pragma unroll
            for (int ni = 0; ni < 8; ni++)
                mma_bf16(acc[mi][ni][0], acc[mi][ni][1], acc[mi][ni][2], acc[mi][ni][3],
                         al0, al1, al2, al3, bh[ni][0], bh[ni][1]);
        }
#pragma unroll
        for (int ni = 0; ni < 8; ni++) {
            int n = nbase + ni * 8 + g;
            uint32_t bl0 = Bl[n * P1 + kw];
            uint32_t bl1 = Bl[n * P1 + kw + 4];
#pragma unroll
            for (int mi = 0; mi < 2; mi++)
                mma_bf16(acc[mi][ni][0], acc[mi][ni][1], acc[mi][ni][2], acc[mi][ni][3],
                         ah[mi][0], ah[mi][1], ah[mi][2], ah[mi][3], bl0, bl1);
        }
    }

    if (y == 0) {
#pragma unroll
        for (int mi = 0; mi < 2; mi++) {
            int r0 = m0 + rbase + mi * 16 + g;
            int r1 = r0 + 8;
            bool v0 = r0 < NN, v1 = r1 < NN;
            float4 p0 = g_pos4[v0 ? r0 : 0];
            float4 p1 = g_pos4[v1 ? r1 : 0];
#pragma unroll
            for (int ni = 0; ni < 8; ni++) {
                int c = nbase + ni * 8 + qc * 2;
                float bx0 = s_bias[c]     + p0.x * s_wx[c]     + p0.y * s_wy[c]     + p0.z * s_wz[c];
                float bx1 = s_bias[c + 1] + p0.x * s_wx[c + 1] + p0.y * s_wy[c + 1] + p0.z * s_wz[c + 1];
                float by0 = s_bias[c]     + p1.x * s_wx[c]     + p1.y * s_wy[c]     + p1.z * s_wz[c];
                float by1 = s_bias[c + 1] + p1.x * s_wx[c + 1] + p1.y * s_wy[c + 1] + p1.z * s_wz[c + 1];
                if (v0) *(float2*)(g_z1 + r0 * 128 + c) = make_float2(acc[mi][ni][0] + bx0, acc[mi][ni][1] + bx1);
                if (v1) *(float2*)(g_z1 + r1 * 128 + c) = make_float2(acc[mi][ni][2] + by0, acc[mi][ni][3] + by1);
            }
        }
    } else {
        float scol[8][2], qcol[8][2];
#pragma unroll
        for (int ni = 0; ni < 8; ni++) {
            scol[ni][0] = 0.0f; scol[ni][1] = 0.0f;
            qcol[ni][0] = 0.0f; qcol[ni][1] = 0.0f;
        }
#pragma unroll
        for (int mi = 0; mi < 2; mi++) {
            int r0 = m0 + rbase + mi * 16 + g;
            int r1 = r0 + 8;
            bool v0 = r0 < NN, v1 = r1 < NN;
#pragma unroll
            for (int ni = 0; ni < 8; ni++) {
                int c = nbase + ni * 8 + qc * 2;
                float s00 = acc[mi][ni][0] + s_bias[c];
                float s01 = acc[mi][ni][1] + s_bias[c + 1];
                float s10 = acc[mi][ni][2] + s_bias[c];
                float s11 = acc[mi][ni][3] + s_bias[c + 1];
                if (v0) {
                    *(float2*)(g_skip + r0 * 128 + c) = make_float2(s00, s01);
                    scol[ni][0] += s00; qcol[ni][0] += s00 * s00;
                    scol[ni][1] += s01; qcol[ni][1] += s01 * s01;
                }
                if (v1) {
                    *(float2*)(g_skip + r1 * 128 + c) = make_float2(s10, s11);
                    scol[ni][0] += s10; qcol[ni][0] += s10 * s10;
                    scol[ni][1] += s11; qcol[ni][1] += s11 * s11;
                }
            }
        }
#pragma unroll
        for (int m = 4; m <= 16; m <<= 1) {
#pragma unroll
            for (int ni = 0; ni < 8; ni++) {
                scol[ni][0] += __shfl_xor_sync(0xffffffffu, scol[ni][0], m);
                scol[ni][1] += __shfl_xor_sync(0xffffffffu, scol[ni][1], m);
                qcol[ni][0] += __shfl_xor_sync(0xffffffffu, qcol[ni][0], m);
                qcol[ni][1] += __shfl_xor_sync(0xffffffffu, qcol[ni][1], m);
            }
        }
        if (g == 0) {
            float* st = g_part + (blockIdx.x & 63) * 256;   // inst 0
#pragma unroll
            for (int ni = 0; ni < 8; ni++) {
                int c = nbase + ni * 8 + qc * 2;
                atomicAdd(&st[c],           scol[ni][0]);
                atomicAdd(&st[c + 1],       scol[ni][1]);
                atomicAdd(&st[128 + c],     qcol[ni][0]);
                atomicAdd(&st[128 + c + 1], qcol[ni][1]);
            }
        }
    }
}

// ---------------- GEMM2 (mma.sync, B from L2, 2 blk/SM): z2 = relu(BN1(agg1))@W2a + b2 + pos@Wp2 ----------------
__global__ __launch_bounds__(256, 2) void k_gemm2_mma(const float* __restrict__ W2,
                                                      const float* __restrict__ b2,
                                                      const float* __restrict__ g1,
                                                      const float* __restrict__ be1) {
    extern __shared__ uint32_t sm[];
    uint32_t* Ah = sm;                   // [128][PSTR]
    uint32_t* Al = Ah + 128 * PSTR;
    __shared__ float sc[128], sf[128];
    __shared__ float s_bias[128], s_wx[128], s_wy[128], s_wz[128];

    int t = threadIdx.x;
    int m0 = blockIdx.x * 128;
    int lane = t & 31, wid = t >> 5;
    int g = lane >> 2, qc = lane & 3;

    if (t < 128) {
        float mu  = g_stat[256 + t] * (1.0f / NN);
        float var = g_stat[256 + 128 + t] * (1.0f / NN) - mu * mu;
        float rs  = rsqrtf(var + 1e-5f);
        float scale = g1[t] * rs;
        sc[t] = scale;
        sf[t] = be1[t] - mu * scale;
        const float* Wp = W2 + 128 * 128;
        s_bias[t] = b2[t];
        s_wx[t] = Wp[t];
        s_wy[t] = Wp[128 + t];
        s_wz[t] = Wp[256 + t];
    }
    __syncthreads();

    for (int idx = t; idx < 128 * 64; idx += 256) {
        int row = idx >> 6, kp = idx & 63, k = kp * 2;
        int grow = m0 + row;
        float2 v = make_float2(0.0f, 0.0f);
        if (grow < NN) v = *(const float2*)(g_agg1 + grow * 128 + k);
        float a0 = fmaxf(fmaf(v.x, sc[k],     sf[k]),     0.0f);
        float a1 = fmaxf(fmaf(v.y, sc[k + 1], sf[k + 1]), 0.0f);
        __nv_bfloat16 h0 = __float2bfloat16(a0);
        __nv_bfloat16 h1 = __float2bfloat16(a1);
        __nv_bfloat162 hh; hh.x = h0; hh.y = h1;
        Ah[row * PSTR + kp] = *(uint32_t*)&hh;
        Al[row * PSTR + kp] = pack_bf16x2(a0 - __bfloat162float(h0), a1 - __bfloat162float(h1));
    }
    __syncthreads();

    int warpM = wid & 3, warpN = wid >> 2;
    int rbase = warpM * 32;
    int nbase = warpN * 64;

    float acc[2][8][4];
#pragma unroll
    for (int mi = 0; mi < 2; mi++)
#pragma unroll
        for (int ni = 0; ni < 8; ni++)
#pragma unroll
            for (int j = 0; j < 4; j++) acc[mi][ni][j] = 0.0f;

#pragma unroll
    for (int k0 = 0; k0 < 8; k0++) {
        int kw = k0 * 8 + qc;
        uint32_t ah[2][4];
#pragma unroll
        for (int mi = 0; mi < 2; mi++) {
            int r = rbase + mi * 16 + g;
            ah[mi][0] = Ah[r * PSTR + kw];
            ah[mi][1] = Ah[(r + 8) * PSTR + kw];
            ah[mi][2] = Ah[r * PSTR + kw + 4];
            ah[mi][3] = Ah[(r + 8) * PSTR + kw + 4];
        }
        uint32_t bh[8][2];
#pragma unroll
        for (int ni = 0; ni < 8; ni++) {
            int n = nbase + ni * 8 + g;
            bh[ni][0] = __ldg(&g_bh[n * PSTR + kw]);
            bh[ni][1] = __ldg(&g_bh[n * PSTR + kw + 4]);
        }
#pragma unroll
        for (int mi = 0; mi < 2; mi++)
#pragma unroll
            for (int ni = 0; ni < 8; ni++)
                mma_bf16(acc[mi][ni][0], acc[mi][ni][1], acc[mi][ni][2], acc[mi][ni][3],
                         ah[mi][0], ah[mi][1], ah[mi][2], ah[mi][3], bh[ni][0], bh[ni][1]);
#pragma unroll
        for (int mi = 0; mi < 2; mi++) {
            int r = rbase + mi * 16 + g;
            uint32_t al0 = Al[r * PSTR + kw];
            uint32_t al1 = Al[(r + 8) * PSTR + kw];
            uint32_t al2 = Al[r * PSTR + kw + 4];
            uint32_t al3 = Al[(r + 8) * PSTR + kw + 4];
#pragma unroll
            for (int ni = 0; ni < 8; ni++)
                mma_bf16(acc[mi][ni][0], acc[mi][ni][1], acc[mi][ni][2], acc[mi][ni][3],
                         al0, al1, al2, al3, bh[ni][0], bh[ni][1]);
        }
#pragma unroll
        for (int ni = 0; ni < 8; ni++) {
            int n = nbase + ni * 8 + g;
            uint32_t bl0 = __ldg(&g_bl[n * PSTR + kw]);
            uint32_t bl1 = __ldg(&g_bl[n * PSTR + kw + 4]);
#pragma unroll
            for (int mi = 0; mi < 2; mi++)
                mma_bf16(acc[mi][ni][0], acc[mi][ni][1], acc[mi][ni][2], acc[mi][ni][3],
                         ah[mi][0], ah[mi][1], ah[mi][2], ah[mi][3], bl0, bl1);
        }
    }

#pragma unroll
    for (int mi = 0; mi < 2; mi++) {
        int r0 = m0 + rbase + mi * 16 + g;
        int r1 = r0 + 8;
        bool v0 = r0 < NN, v1 = r1 < NN;
        float4 p0 = g_pos4[v0 ? r0 : 0];
        float4 p1 = g_pos4[v1 ? r1 : 0];
#pragma unroll
        for (int ni = 0; ni < 8; ni++) {
            int c = nbase + ni * 8 + qc * 2;
            float bx0 = s_bias[c]     + p0.x * s_wx[c]     + p0.y * s_wy[c]     + p0.z * s_wz[c];
            float bx1 = s_bias[c + 1] + p0.x * s_wx[c + 1] + p0.y * s_wy[c + 1] + p0.z * s_wz[c + 1];
            float by0 = s_bias[c]     + p1.x * s_wx[c]     + p1.y * s_wy[c]     + p1.z * s_wz[c];
            float by1 = s_bias[c + 1] + p1.x * s_wx[c + 1] + p1.y * s_wy[c + 1] + p1.z * s_wz[c + 1];
            if (v0) *(float2*)(g_z2 + r0 * 128 + c) = make_float2(acc[mi][ni][0] + bx0, acc[mi][ni][1] + bx1);
            if (v1) *(float2*)(g_z2 + r1 * 128 + c) = make_float2(acc[mi][ni][2] + by0, acc[mi][ni][3] + by1);
        }
    }
}

// ---------------- aggregation ----------------
__global__ __launch_bounds__(256) void k_agg(const float* __restrict__ Wp, int phase, int inst) {
    __shared__ float shs[8][128];
    __shared__ float shq[8][128];
    int w    = threadIdx.x >> 5;
    int gw   = blockIdx.x * 8 + w;
    int lane = threadIdx.x & 31;
    int f = lane * 4;
    const float* __restrict__ z = phase ? g_z2 : g_z1;
    int cnt = g_deg[gw];
    const int* __restrict__ bucket = g_csr + gw * STRIDE;
    float ninf = __int_as_float(0xff800000);
    float4 acc = make_float4(ninf, ninf, ninf, ninf);
#pragma unroll 8
    for (int e = 0; e < cnt; e++) {
        int s = __ldg(&bucket[e]);
        float4 v = *(const float4*)(z + s * 128 + f);
        acc.x = fmaxf(acc.x, v.x);
        acc.y = fmaxf(acc.y, v.y);
        acc.z = fmaxf(acc.z, v.z);
        acc.w = fmaxf(acc.w, v.w);
    }
    float4 o;
    if (cnt == 0) {
        o = make_float4(0, 0, 0, 0);
    } else {
        float4 dp = g_pos4[gw];
        float4 wx = *(const float4*)(Wp + f);
        float4 wy = *(const float4*)(Wp + 128 + f);
        float4 wz = *(const float4*)(Wp + 256 + f);
        o.x = acc.x - (dp.x * wx.x + dp.y * wy.x + dp.z * wz.x);
        o.y = acc.y - (dp.x * wx.y + dp.y * wy.y + dp.z * wz.y);
        o.z = acc.z - (dp.x * wx.z + dp.y * wy.z + dp.z * wz.z);
        o.w = acc.w - (dp.x * wx.w + dp.y * wy.w + dp.z * wz.w);
    }
    float* oo = phase ? g_agg2 : g_agg1;
    *(float4*)(oo + gw * 128 + f) = o;

    *(float4*)&shs[w][f] = o;
    float4 q = make_float4(o.x * o.x, o.y * o.y, o.z * o.z, o.w * o.w);
    *(float4*)&shq[w][f] = q;
    __syncthreads();
    int t = threadIdx.x;
    if (t < 128) {
        float a = 0.0f, b = 0.0f;
#pragma unroll
        for (int w2 = 0; w2 < 8; w2++) {
            a += shs[w2][t];
            b += shq[w2][t];
        }
        float* st = g_part + (inst * 64 + (blockIdx.x & 63)) * 256;
        atomicAdd(&st[t], a);
        atomicAdd(&st[128 + t], b);
    }
}

// ---------------- output ----------------
__global__ __launch_bounds__(256) void k_out(float* __restrict__ out,
                                             const float* __restrict__ gl,
                                             const float* __restrict__ bel,
                                             const float* __restrict__ g2,
                                             const float* __restrict__ be2) {
    __shared__ float cl[128], hl[128], c2[128], h2[128];
    int t = threadIdx.x;
    if (t < 128) {
        float mu  = g_stat[t] * (1.0f / NN);
        float var = g_stat[128 + t] * (1.0f / NN) - mu * mu;
        float rs  = rsqrtf(var + 1e-5f);
        float s0  = gl[t] * rs;
        cl[t] = s0;
        hl[t] = bel[t] - mu * s0;
    } else {
        int f = t - 128;
        float mu  = g_stat[512 + f] * (1.0f / NN);
        float var = g_stat[512 + 128 + f] * (1.0f / NN) - mu * mu;
        float rs  = rsqrtf(var + 1e-5f);
        float s2  = g2[f] * rs;
        c2[f] = s2;
        h2[f] = be2[f] - mu * s2;
    }
    __syncthreads();
    int i = blockIdx.x * 8 + (t >> 5);
    int f = (t & 31) * 4;
    float4 a  = *(const float4*)(g_agg2 + i * 128 + f);
    float4 s  = *(const float4*)(g_skip + i * 128 + f);
    float4 o;
    o.x = fmaxf(fmaf(a.x, c2[f],     h2[f])     + fmaf(s.x, cl[f],     hl[f]),     0.0f);
    o.y = fmaxf(fmaf(a.y, c2[f + 1], h2[f + 1]) + fmaf(s.y, cl[f + 1], hl[f + 1]), 0.0f);
    o.z = fmaxf(fmaf(a.z, c2[f + 2], h2[f + 2]) + fmaf(s.z, cl[f + 2], hl[f + 2]), 0.0f);
    o.w = fmaxf(fmaf(a.w, c2[f + 3], h2[f + 3]) + fmaf(s.w, cl[f + 3], hl[f + 3]), 0.0f);
    *(float4*)(out + i * 128 + f) = o;
}

// ---------------- launcher ----------------
extern "C" void kernel_launch(void* const* d_in, const int* in_sizes, int n_in,
                              void* d_out, int out_size) {
    const float* x   = (const float*)d_in[0];
    const float* pos = (const float*)d_in[1];
    const int*   ei  = (const int*)  d_in[2];
    const float* W1  = (const float*)d_in[3];
    const float* b1  = (const float*)d_in[4];
    const float* g1  = (const float*)d_in[5];
    const float* be1 = (const float*)d_in[6];
    const float* W2  = (const float*)d_in[7];
    const float* b2  = (const float*)d_in[8];
    const float* g2  = (const float*)d_in[9];
    const float* be2 = (const float*)d_in[10];
    const float* Wl  = (const float*)d_in[11];
    const float* bl  = (const float*)d_in[12];
    const float* gl  = (const float*)d_in[13];
    const float* bel = (const float*)d_in[14];
    float* out = (float*)d_out;

    int gridE = (EE + 255) / 256;
    int gridN = (NN + 255) / 256;
    int gridA = NN / 8;                       // 6250
    int gridM = (NN + 127) / 128;             // 391
    int smem1 = 4 * 128 * P1 * 4;             // 73728
    int smem2 = 2 * 128 * PSTR * 4;           // 69632 (A only; B streamed from L2)

    cudaFuncSetAttribute(k_gemm1_mma, cudaFuncAttributeMaxDynamicSharedMemorySize, smem1);
    cudaFuncSetAttribute(k_gemm2_mma, cudaFuncAttributeMaxDynamicSharedMemorySize, smem2);

    k_init<<<gridN, 256>>>(pos);
    k_build<<<gridE, 256>>>(ei);
    k_prep<<<64, 256>>>(W1, Wl, W2);

    k_gemm1_mma<<<dim3(gridM, 2), 256, smem1>>>(x, W1, b1, bl);   // + skip stats (inst 0)

    k_agg<<<gridA, 256>>>(W1 + 64 * 128, 0, 1);                   // + agg1 stats (inst 1)
    k_red2<<<1, 512>>>(0, 1);

    k_gemm2_mma<<<gridM, 256, smem2>>>(W2, b2, g1, be1);

    k_agg<<<gridA, 256>>>(W2 + 128 * 128, 1, 2);                  // + agg2 stats (inst 2)
    k_red2<<<1, 512>>>(2, -1);

    k_out<<<gridA, 256>>>(out, gl, bel, g2, be2);
}